// round 10
// baseline (speedup 1.0000x reference)
#include <cuda_runtime.h>
#include <cuda_fp16.h>
#include <math.h>

// ---------------------------------------------------------------------------
// GAT 3-layer pipeline. R10 = R9 with the folded-self-loop denominator fix:
// reduce per-lane edge denom BEFORE adding the (lane-uniform) self-loop term.
// ---------------------------------------------------------------------------

#define MAXN 50048
#define MAXE 600064

__device__ __half   g_h[MAXN * 128];
__device__ unsigned g_xf[MAXN * 128];
__device__ unsigned g_bufAf[MAXN * 128];
__device__ unsigned g_bufBf[MAXN * 128];
__device__ unsigned g_wf0[16384];
__device__ unsigned g_wf1[16384];
__device__ unsigned g_wf2[8192];
__device__ float    g_ss[MAXN];
__device__ float    g_sd[MAXN];
__device__ float    g_cee[3 * MAXE];
__device__ int      g_deg[MAXN];
__device__ int      g_off[MAXN + 1];
__device__ int      g_cur[MAXN];
__device__ int      g_csrc[MAXE];
__device__ float    g_v[24];
__device__ int      g_is64;

__device__ __forceinline__ int get_idx(const void* ei, int i) {
    if (g_is64) return (int)((const long long*)ei)[i];
    return ((const int*)ei)[i];
}

__device__ __forceinline__ unsigned f2tf32(float x) {
    unsigned u;
    asm("cvt.rna.tf32.f32 %0, %1;" : "=r"(u) : "f"(x));
    return u;
}

__device__ __forceinline__ void mma_k8(float4& c, unsigned a0, unsigned a1,
                                       unsigned a2, unsigned a3,
                                       unsigned b0, unsigned b1) {
    asm volatile(
        "mma.sync.aligned.m16n8k8.row.col.f32.tf32.tf32.f32 "
        "{%0,%1,%2,%3}, {%4,%5,%6,%7}, {%8,%9}, {%0,%1,%2,%3};"
        : "+f"(c.x), "+f"(c.y), "+f"(c.z), "+f"(c.w)
        : "r"(a0), "r"(a1), "r"(a2), "r"(a3), "r"(b0), "r"(b1));
}

// ---------------------------------------------------------------------------
__global__ void xform_kernel(const float* __restrict__ X,
                             const float* __restrict__ W0,
                             const float* __restrict__ W1,
                             const float* __restrict__ W2, int M) {
    int f = blockIdx.x * blockDim.x + threadIdx.x;
    if (f < M * 32) {
        int r = f >> 5, c4 = (f & 31) << 2;
        float4 v = *(const float4*)(X + (size_t)r * 128 + c4);
        int kb = c4 >> 3, j = (c4 >> 2) & 1;
        unsigned* base = g_xf + (size_t)r * 128 + kb * 8 + j;
        base[0] = f2tf32(v.x); base[2] = f2tf32(v.y);
        base[4] = f2tf32(v.z); base[6] = f2tf32(v.w);
        return;
    }
    int idx = f - M * 32;
    int l, e;
    if (idx < 16384)       { l = 0; e = idx; }
    else if (idx < 32768)  { l = 1; e = idx - 16384; }
    else if (idx < 40960)  { l = 2; e = idx - 32768; }
    else return;
    int BN = (l == 2) ? 64 : 128;
    int k = e / BN, n = e % BN;
    const float* W = (l == 0) ? W0 : (l == 1) ? W1 : W2;
    unsigned* Wf = (l == 0) ? g_wf0 : (l == 1) ? g_wf1 : g_wf2;
    int lane = (n & 7) * 4 + (k & 3);
    int j = (k >> 2) & 1;
    int word = (((n >> 3) * 16 + (k >> 3)) * 32 + lane) * 2 + j;
    Wf[word] = f2tf32(W[k * BN + n]);
}

__global__ void init_kernel(const int* __restrict__ eiw, int forced,
                            const float* We0, const float* ae0,
                            const float* We1, const float* ae1,
                            const float* We2, const float* ae2, int n) {
    int i = blockIdx.x * blockDim.x + threadIdx.x;
    for (int t = i; t < n; t += gridDim.x * blockDim.x) g_deg[t] = 0;
    if (blockIdx.x == 0) {
        if (threadIdx.x == 0) {
            if (forced >= 0) g_is64 = forced;
            else {
                int is64 = 1;
                for (int j = 1; j < 32; j += 2)
                    if (eiw[j] != 0) is64 = 0;
                g_is64 = is64;
            }
        }
        int t = (int)threadIdx.x - 32;
        if (t >= 0 && t < 24) {
            int l = t / 8, j = t % 8;
            const float* We = (l == 0) ? We0 : (l == 1) ? We1 : We2;
            const float* ae = (l == 0) ? ae0 : (l == 1) ? ae1 : ae2;
            int C = (l == 2) ? 64 : 128;
            float s = 0.f;
            for (int c = 0; c < C; c++) s += We[j * C + c] * ae[c];
            g_v[l * 8 + j] = s;
        }
    }
}

__global__ void count_kernel(const void* __restrict__ ei, int E, int n) {
    int e = blockIdx.x * blockDim.x + threadIdx.x;
    if (e >= E) return;
    int d = get_idx(ei, E + e);
    if ((unsigned)d < (unsigned)n) atomicAdd(&g_deg[d], 1);
}

__global__ void scan_kernel(int n) {
    __shared__ int wsum[32];
    int tid = threadIdx.x;
    int per = (n + 1023) / 1024;
    int st = tid * per;
    int en = min(st + per, n);
    int s = 0;
    for (int i = st; i < en; i++) s += g_deg[i];
    int lane = tid & 31, wid = tid >> 5;
    int v = s;
#pragma unroll
    for (int o = 1; o < 32; o <<= 1) {
        int t = __shfl_up_sync(0xffffffffu, v, o);
        if (lane >= o) v += t;
    }
    if (lane == 31) wsum[wid] = v;
    __syncthreads();
    if (wid == 0) {
        int w = wsum[lane];
#pragma unroll
        for (int o = 1; o < 32; o <<= 1) {
            int t = __shfl_up_sync(0xffffffffu, w, o);
            if (lane >= o) w += t;
        }
        wsum[lane] = w;
    }
    __syncthreads();
    int base = v - s + ((wid > 0) ? wsum[wid - 1] : 0);
    for (int i = st; i < en; i++) {
        g_off[i] = base;
        g_cur[i] = base;
        base += g_deg[i];
    }
    if (tid == 1023) g_off[n] = base;
}

__global__ void edgefill_kernel(const float* __restrict__ ea,
                                const void* __restrict__ ei,
                                int E, int n) {
    int e = blockIdx.x * blockDim.x + threadIdx.x;
    if (e >= E) return;
    int s = get_idx(ei, e);
    int d = get_idx(ei, E + e);
    if ((unsigned)d >= (unsigned)n || (unsigned)s >= (unsigned)n) return;
    float a[8];
#pragma unroll
    for (int j = 0; j < 8; j++) a[j] = ea[e * 8 + j];
    int p = atomicAdd(&g_cur[d], 1);
    if (p >= MAXE) return;
    g_csrc[p] = s;
#pragma unroll
    for (int l = 0; l < 3; l++) {
        float sv = 0.f;
#pragma unroll
        for (int j = 0; j < 8; j++) sv += a[j] * g_v[l * 8 + j];
        g_cee[l * MAXE + p] = sv;
    }
}

// ---------------------------------------------------------------------------
// Smem-free tf32 GEMM, BM=64, warp tile 16 x (BN/2); H stored fp16.
template <int BN>
__global__ void __launch_bounds__(256, 3)
gemm_frag(const unsigned* __restrict__ Af, const unsigned* __restrict__ Wf,
          const float* __restrict__ as_, const float* __restrict__ ad_,
          __half* __restrict__ H, int M) {
    const int NT = BN / 16;
    __shared__ float Sp[256];
    int tid = threadIdx.x;
    int lane = tid & 31, wid = tid >> 5;
    int g = lane >> 2, tq = lane & 3;
    int wr = wid & 3;
    int wc = wid >> 2;
    int row0 = blockIdx.x * 64;

    float4 acc[NT];
#pragma unroll
    for (int nt = 0; nt < NT; nt++) acc[nt] = make_float4(0.f, 0.f, 0.f, 0.f);

    const unsigned* pa0 = Af + (size_t)(row0 + wr * 16 + g) * 128 + tq * 2;
    const unsigned* pa1 = pa0 + 8 * 128;
    const unsigned* pb = Wf + ((size_t)(wc * NT) * 16 * 32 + lane) * 2;

#pragma unroll
    for (int kb = 0; kb < 16; kb++) {
        uint2 au = *(const uint2*)(pa0 + kb * 8);
        uint2 av = *(const uint2*)(pa1 + kb * 8);
#pragma unroll
        for (int nt = 0; nt < NT; nt++) {
            uint2 b = *(const uint2*)(pb + (nt * 16 + kb) * 64);
            mma_k8(acc[nt], au.x, av.x, au.y, av.y, b.x, b.y);
        }
    }

    int rA = row0 + wr * 16 + g;
    float s1l = 0.f, s2l = 0.f, s1h = 0.f, s2h = 0.f;
#pragma unroll
    for (int nt = 0; nt < NT; nt++) {
        int c0 = wc * (BN / 2) + nt * 8 + 2 * tq;
        float w1 = as_[c0], w1b = as_[c0 + 1];
        float w2 = ad_[c0], w2b = ad_[c0 + 1];
        float4 c = acc[nt];
        s1l += c.x * w1 + c.y * w1b;
        s2l += c.x * w2 + c.y * w2b;
        s1h += c.z * w1 + c.w * w1b;
        s2h += c.z * w2 + c.w * w2b;
        if (rA < M)
            *(__half2*)&H[(size_t)rA * BN + c0] = __floats2half2_rn(c.x, c.y);
        if (rA + 8 < M)
            *(__half2*)&H[(size_t)(rA + 8) * BN + c0] = __floats2half2_rn(c.z, c.w);
    }
#pragma unroll
    for (int o = 1; o < 4; o <<= 1) {
        s1l += __shfl_xor_sync(0xffffffffu, s1l, o);
        s2l += __shfl_xor_sync(0xffffffffu, s2l, o);
        s1h += __shfl_xor_sync(0xffffffffu, s1h, o);
        s2h += __shfl_xor_sync(0xffffffffu, s2h, o);
    }
    if (tq == 0) {
        int rib = wr * 16 + g;
        Sp[wc * 64 + rib]           = s1l;
        Sp[wc * 64 + rib + 8]       = s1h;
        Sp[128 + wc * 64 + rib]     = s2l;
        Sp[128 + wc * 64 + rib + 8] = s2h;
    }
    __syncthreads();
    if (tid < 64) {
        int r = row0 + tid;
        if (r < M) {
            g_ss[r] = Sp[tid] + Sp[64 + tid];
            g_sd[r] = Sp[128 + tid] + Sp[192 + tid];
        }
    }
}

// ---------------------------------------------------------------------------
// Warp-per-dst online softmax + aggregation with folded self-loop.
__global__ void aggregate128(int layer, const float* __restrict__ bias,
                             unsigned* __restrict__ outf, int n) {
    const float* cee = g_cee + (size_t)layer * MAXE;
    int node = blockIdx.x * (blockDim.x >> 5) + (threadIdx.x >> 5);
    int lane = threadIdx.x & 31;
    if (node >= n) return;
    int e0 = g_off[node], e1 = g_off[node + 1];
    float sdn = g_sd[node];

    float m = -INFINITY, denom = 0.f, csum = 0.f;
    float4 acc = make_float4(0.f, 0.f, 0.f, 0.f);

    for (int jb = e0; jb < e1; jb += 32) {
        int j = jb + lane;
        float a = -INFINITY;
        int s = 0;
        if (j < e1) {
            s = g_csrc[j];
            float cv = cee[j];
            csum += cv;
            a = g_ss[s] + sdn + cv;
            a = (a > 0.f) ? a : 0.2f * a;
        }
        float bm = a;
#pragma unroll
        for (int o = 16; o; o >>= 1) bm = fmaxf(bm, __shfl_xor_sync(0xffffffffu, bm, o));
        float newm = fmaxf(m, bm);
        float scale = __expf(m - newm);
        denom *= scale;
        acc.x *= scale; acc.y *= scale; acc.z *= scale; acc.w *= scale;
        m = newm;
        float ex = (j < e1) ? __expf(a - m) : 0.f;
        denom += ex;
        int kmax = min(e1 - jb, 32);
        for (int k = 0; k < kmax; k += 8) {
            float ef[8]; int sv[8];
#pragma unroll
            for (int q = 0; q < 8; q++) {
                ef[q] = __shfl_sync(0xffffffffu, ex, k + q);
                sv[q] = __shfl_sync(0xffffffffu, s, k + q);
            }
            __half2 hv[8][2];
#pragma unroll
            for (int q = 0; q < 8; q++) {
                const __half2* hp = (const __half2*)(g_h + (size_t)sv[q] * 128) + lane * 2;
                hv[q][0] = hp[0]; hv[q][1] = hp[1];
            }
#pragma unroll
            for (int q = 0; q < 8; q++) {
                float2 lo = __half22float2(hv[q][0]);
                float2 hi = __half22float2(hv[q][1]);
                acc.x += ef[q] * lo.x; acc.y += ef[q] * lo.y;
                acc.z += ef[q] * hi.x; acc.w += ef[q] * hi.y;
            }
        }
    }
    // Reduce per-lane partials FIRST (fix: denom must be lane-uniform before
    // the self-loop term is added exactly once).
#pragma unroll
    for (int o = 16; o; o >>= 1) {
        csum  += __shfl_xor_sync(0xffffffffu, csum, o);
        denom += __shfl_xor_sync(0xffffffffu, denom, o);
    }
    // self-loop: ee = mean(cee) over incoming; feature = h[node]
    float invd = 1.f / fmaxf((float)(e1 - e0), 1.f);
    float aself = g_ss[node] + sdn + csum * invd;
    aself = (aself > 0.f) ? aself : 0.2f * aself;
    float newm = fmaxf(m, aself);
    float scale = __expf(m - newm);
    float exs = __expf(aself - newm);
    denom = denom * scale + exs;
    acc.x *= scale; acc.y *= scale; acc.z *= scale; acc.w *= scale;
    {
        const __half2* hp = (const __half2*)(g_h + (size_t)node * 128) + lane * 2;
        float2 lo = __half22float2(hp[0]);
        float2 hi = __half22float2(hp[1]);
        acc.x += exs * lo.x; acc.y += exs * lo.y;
        acc.z += exs * hi.x; acc.w += exs * hi.y;
    }
    float inv = 1.f / (denom + 1e-16f);
    float4 b = *(const float4*)(bias + lane * 4);
    float4 r;
    r.x = fmaxf(acc.x * inv + b.x, 0.f);
    r.y = fmaxf(acc.y * inv + b.y, 0.f);
    r.z = fmaxf(acc.z * inv + b.z, 0.f);
    r.w = fmaxf(acc.w * inv + b.w, 0.f);
    unsigned* base = outf + (size_t)node * 128 + (lane >> 1) * 8 + (lane & 1);
    base[0] = f2tf32(r.x); base[2] = f2tf32(r.y);
    base[4] = f2tf32(r.z); base[6] = f2tf32(r.w);
}

__global__ void aggregate64(int layer, const float* __restrict__ bias,
                            float* __restrict__ out, int n) {
    const float* cee = g_cee + (size_t)layer * MAXE;
    int node = blockIdx.x * (blockDim.x >> 5) + (threadIdx.x >> 5);
    int lane = threadIdx.x & 31;
    if (node >= n) return;
    int e0 = g_off[node], e1 = g_off[node + 1];
    float sdn = g_sd[node];

    float m = -INFINITY, denom = 0.f, csum = 0.f;
    float2 acc = make_float2(0.f, 0.f);

    for (int jb = e0; jb < e1; jb += 32) {
        int j = jb + lane;
        float a = -INFINITY;
        int s = 0;
        if (j < e1) {
            s = g_csrc[j];
            float cv = cee[j];
            csum += cv;
            a = g_ss[s] + sdn + cv;
            a = (a > 0.f) ? a : 0.2f * a;
        }
        float bm = a;
#pragma unroll
        for (int o = 16; o; o >>= 1) bm = fmaxf(bm, __shfl_xor_sync(0xffffffffu, bm, o));
        float newm = fmaxf(m, bm);
        float scale = __expf(m - newm);
        denom *= scale;
        acc.x *= scale; acc.y *= scale;
        m = newm;
        float ex = (j < e1) ? __expf(a - m) : 0.f;
        denom += ex;
        int kmax = min(e1 - jb, 32);
        for (int k = 0; k < kmax; k += 8) {
            float ef[8]; int sv[8];
#pragma unroll
            for (int q = 0; q < 8; q++) {
                ef[q] = __shfl_sync(0xffffffffu, ex, k + q);
                sv[q] = __shfl_sync(0xffffffffu, s, k + q);
            }
            __half2 hv[8];
#pragma unroll
            for (int q = 0; q < 8; q++)
                hv[q] = *((const __half2*)(g_h + (size_t)sv[q] * 64) + lane);
#pragma unroll
            for (int q = 0; q < 8; q++) {
                float2 lo = __half22float2(hv[q]);
                acc.x += ef[q] * lo.x; acc.y += ef[q] * lo.y;
            }
        }
    }
#pragma unroll
    for (int o = 16; o; o >>= 1) {
        csum  += __shfl_xor_sync(0xffffffffu, csum, o);
        denom += __shfl_xor_sync(0xffffffffu, denom, o);
    }
    float invd = 1.f / fmaxf((float)(e1 - e0), 1.f);
    float aself = g_ss[node] + sdn + csum * invd;
    aself = (aself > 0.f) ? aself : 0.2f * aself;
    float newm = fmaxf(m, aself);
    float scale = __expf(m - newm);
    float exs = __expf(aself - newm);
    denom = denom * scale + exs;
    acc.x *= scale; acc.y *= scale;
    {
        float2 lo = __half22float2(*((const __half2*)(g_h + (size_t)node * 64) + lane));
        acc.x += exs * lo.x; acc.y += exs * lo.y;
    }
    float inv = 1.f / (denom + 1e-16f);
    float2 b = *(const float2*)(bias + lane * 2);
    float2 r;
    r.x = acc.x * inv + b.x;
    r.y = acc.y * inv + b.y;
    *(float2*)(out + (size_t)node * 64 + lane * 2) = r;
}

extern "C" void kernel_launch(void* const* d_in, const int* in_sizes, int n_in,
                              void* d_out, int out_size) {
    const float* x      = (const float*)d_in[0];
    const void*  ei     = d_in[1];
    const float* ea     = (const float*)d_in[2];
    const float* W[3]  = {(const float*)d_in[3],  (const float*)d_in[9],  (const float*)d_in[15]};
    const float* As_[3]= {(const float*)d_in[4],  (const float*)d_in[10], (const float*)d_in[16]};
    const float* Ad[3] = {(const float*)d_in[5],  (const float*)d_in[11], (const float*)d_in[17]};
    const float* We[3] = {(const float*)d_in[6],  (const float*)d_in[12], (const float*)d_in[18]};
    const float* Ae[3] = {(const float*)d_in[7],  (const float*)d_in[13], (const float*)d_in[19]};
    const float* Bb[3] = {(const float*)d_in[8],  (const float*)d_in[14], (const float*)d_in[20]};

    int N = in_sizes[0] / 128;
    int E = in_sizes[2] / 8;
    int forced = (in_sizes[1] == 4 * E) ? 1 : -1;

    static __half* h = nullptr;
    static unsigned *xf = nullptr, *bufAf = nullptr, *bufBf = nullptr;
    static unsigned *wf0 = nullptr, *wf1 = nullptr, *wf2 = nullptr;
    if (!h) {
        cudaGetSymbolAddress((void**)&h,     g_h);
        cudaGetSymbolAddress((void**)&xf,    g_xf);
        cudaGetSymbolAddress((void**)&bufAf, g_bufAf);
        cudaGetSymbolAddress((void**)&bufBf, g_bufBf);
        cudaGetSymbolAddress((void**)&wf0,   g_wf0);
        cudaGetSymbolAddress((void**)&wf1,   g_wf1);
        cudaGetSymbolAddress((void**)&wf2,   g_wf2);
    }

    int gb = (N + 63) / 64;
    int nb = (N + 7) / 8;

    xform_kernel<<<(N * 32 + 40960 + 255) / 256, 256>>>(x, W[0], W[1], W[2], N);
    init_kernel<<<(N + 255) / 256, 256>>>((const int*)ei, forced,
                                          We[0], Ae[0], We[1], Ae[1], We[2], Ae[2], N);
    count_kernel<<<(E + 255) / 256, 256>>>(ei, E, N);
    gemm_frag<128><<<gb, 256>>>(xf, wf0, As_[0], Ad[0], h, N);
    scan_kernel<<<1, 1024>>>(N);
    edgefill_kernel<<<(E + 255) / 256, 256>>>(ea, ei, E, N);
    aggregate128<<<nb, 256>>>(0, Bb[0], bufAf, N);
    gemm_frag<128><<<gb, 256>>>(bufAf, wf1, As_[1], Ad[1], h, N);
    aggregate128<<<nb, 256>>>(1, Bb[1], bufBf, N);
    gemm_frag<64><<<gb, 256>>>(bufBf, wf2, As_[2], Ad[2], h, N);
    aggregate64<<<nb, 256>>>(2, Bb[2], (float*)d_out, N);
}

// round 11
// speedup vs baseline: 1.0760x; 1.0760x over previous
#include <cuda_runtime.h>
#include <cuda_fp16.h>
#include <math.h>

// ---------------------------------------------------------------------------
// GAT 3-layer pipeline. R11: GEMM reverted to measured-best R8 shape (BM=128,
// 2 CTAs/SM); CSR payload packed into one int4 {src, cee0, cee1, cee2} ->
// edgefill does 1 STG.128/edge, aggregates do 1 LDG.128/edge for scores.
// Folded self-loop aggregation (R10 fix) retained.
// ---------------------------------------------------------------------------

#define MAXN 50048
#define MAXE 600064

__device__ __half   g_h[MAXN * 128];
__device__ unsigned g_xf[MAXN * 128];
__device__ unsigned g_bufAf[MAXN * 128];
__device__ unsigned g_bufBf[MAXN * 128];
__device__ unsigned g_wf0[16384];
__device__ unsigned g_wf1[16384];
__device__ unsigned g_wf2[8192];
__device__ float    g_ss[MAXN];
__device__ float    g_sd[MAXN];
__device__ int4     g_csr[MAXE];          // {src, cee0, cee1, cee2}
__device__ int      g_deg[MAXN];
__device__ int      g_off[MAXN + 1];
__device__ int      g_cur[MAXN];
__device__ float    g_v[24];
__device__ int      g_is64;

__device__ __forceinline__ int get_idx(const void* ei, int i) {
    if (g_is64) return (int)((const long long*)ei)[i];
    return ((const int*)ei)[i];
}

__device__ __forceinline__ unsigned f2tf32(float x) {
    unsigned u;
    asm("cvt.rna.tf32.f32 %0, %1;" : "=r"(u) : "f"(x));
    return u;
}

__device__ __forceinline__ void mma_k8(float4& c, unsigned a0, unsigned a1,
                                       unsigned a2, unsigned a3,
                                       unsigned b0, unsigned b1) {
    asm volatile(
        "mma.sync.aligned.m16n8k8.row.col.f32.tf32.tf32.f32 "
        "{%0,%1,%2,%3}, {%4,%5,%6,%7}, {%8,%9}, {%0,%1,%2,%3};"
        : "+f"(c.x), "+f"(c.y), "+f"(c.z), "+f"(c.w)
        : "r"(a0), "r"(a1), "r"(a2), "r"(a3), "r"(b0), "r"(b1));
}

// ---------------------------------------------------------------------------
__global__ void xform_kernel(const float* __restrict__ X,
                             const float* __restrict__ W0,
                             const float* __restrict__ W1,
                             const float* __restrict__ W2, int M) {
    int f = blockIdx.x * blockDim.x + threadIdx.x;
    if (f < M * 32) {
        int r = f >> 5, c4 = (f & 31) << 2;
        float4 v = *(const float4*)(X + (size_t)r * 128 + c4);
        int kb = c4 >> 3, j = (c4 >> 2) & 1;
        unsigned* base = g_xf + (size_t)r * 128 + kb * 8 + j;
        base[0] = f2tf32(v.x); base[2] = f2tf32(v.y);
        base[4] = f2tf32(v.z); base[6] = f2tf32(v.w);
        return;
    }
    int idx = f - M * 32;
    int l, e;
    if (idx < 16384)       { l = 0; e = idx; }
    else if (idx < 32768)  { l = 1; e = idx - 16384; }
    else if (idx < 40960)  { l = 2; e = idx - 32768; }
    else return;
    int BN = (l == 2) ? 64 : 128;
    int k = e / BN, n = e % BN;
    const float* W = (l == 0) ? W0 : (l == 1) ? W1 : W2;
    unsigned* Wf = (l == 0) ? g_wf0 : (l == 1) ? g_wf1 : g_wf2;
    int lane = (n & 7) * 4 + (k & 3);
    int j = (k >> 2) & 1;
    int word = (((n >> 3) * 16 + (k >> 3)) * 32 + lane) * 2 + j;
    Wf[word] = f2tf32(W[k * BN + n]);
}

__global__ void init_kernel(const int* __restrict__ eiw, int forced,
                            const float* We0, const float* ae0,
                            const float* We1, const float* ae1,
                            const float* We2, const float* ae2, int n) {
    int i = blockIdx.x * blockDim.x + threadIdx.x;
    for (int t = i; t < n; t += gridDim.x * blockDim.x) g_deg[t] = 0;
    if (blockIdx.x == 0) {
        if (threadIdx.x == 0) {
            if (forced >= 0) g_is64 = forced;
            else {
                int is64 = 1;
                for (int j = 1; j < 32; j += 2)
                    if (eiw[j] != 0) is64 = 0;
                g_is64 = is64;
            }
        }
        int t = (int)threadIdx.x - 32;
        if (t >= 0 && t < 24) {
            int l = t / 8, j = t % 8;
            const float* We = (l == 0) ? We0 : (l == 1) ? We1 : We2;
            const float* ae = (l == 0) ? ae0 : (l == 1) ? ae1 : ae2;
            int C = (l == 2) ? 64 : 128;
            float s = 0.f;
            for (int c = 0; c < C; c++) s += We[j * C + c] * ae[c];
            g_v[l * 8 + j] = s;
        }
    }
}

__global__ void count_kernel(const void* __restrict__ ei, int E, int n) {
    int e = blockIdx.x * blockDim.x + threadIdx.x;
    if (e >= E) return;
    int d = get_idx(ei, E + e);
    if ((unsigned)d < (unsigned)n) atomicAdd(&g_deg[d], 1);
}

__global__ void scan_kernel(int n) {
    __shared__ int wsum[32];
    int tid = threadIdx.x;
    int per = (n + 1023) / 1024;
    int st = tid * per;
    int en = min(st + per, n);
    int s = 0;
    for (int i = st; i < en; i++) s += g_deg[i];
    int lane = tid & 31, wid = tid >> 5;
    int v = s;
#pragma unroll
    for (int o = 1; o < 32; o <<= 1) {
        int t = __shfl_up_sync(0xffffffffu, v, o);
        if (lane >= o) v += t;
    }
    if (lane == 31) wsum[wid] = v;
    __syncthreads();
    if (wid == 0) {
        int w = wsum[lane];
#pragma unroll
        for (int o = 1; o < 32; o <<= 1) {
            int t = __shfl_up_sync(0xffffffffu, w, o);
            if (lane >= o) w += t;
        }
        wsum[lane] = w;
    }
    __syncthreads();
    int base = v - s + ((wid > 0) ? wsum[wid - 1] : 0);
    for (int i = st; i < en; i++) {
        g_off[i] = base;
        g_cur[i] = base;
        base += g_deg[i];
    }
    if (tid == 1023) g_off[n] = base;
}

__global__ void edgefill_kernel(const float* __restrict__ ea,
                                const void* __restrict__ ei,
                                int E, int n) {
    int e = blockIdx.x * blockDim.x + threadIdx.x;
    if (e >= E) return;
    int s = get_idx(ei, e);
    int d = get_idx(ei, E + e);
    if ((unsigned)d >= (unsigned)n || (unsigned)s >= (unsigned)n) return;
    float a[8];
#pragma unroll
    for (int j = 0; j < 8; j++) a[j] = ea[e * 8 + j];
    float c[3];
#pragma unroll
    for (int l = 0; l < 3; l++) {
        float sv = 0.f;
#pragma unroll
        for (int j = 0; j < 8; j++) sv += a[j] * g_v[l * 8 + j];
        c[l] = sv;
    }
    int p = atomicAdd(&g_cur[d], 1);
    if (p >= MAXE) return;
    g_csr[p] = make_int4(s, __float_as_int(c[0]), __float_as_int(c[1]),
                         __float_as_int(c[2]));
}

// ---------------------------------------------------------------------------
// Smem-free tf32 GEMM + fused scores; H stored fp16. (R8 measured-best shape:
// BM=128, warp grid 4x2, MI=2, 2 CTAs/SM.)
template <int BN>
__global__ void __launch_bounds__(256, 2)
gemm_frag(const unsigned* __restrict__ Af, const unsigned* __restrict__ Wf,
          const float* __restrict__ as_, const float* __restrict__ ad_,
          __half* __restrict__ H, int M) {
    const int MI = (BN == 128) ? 2 : 1;
    const int RPW = (BN == 128) ? 32 : 16;
    __shared__ float Sp[512];
    int tid = threadIdx.x;
    int lane = tid & 31, wid = tid >> 5;
    int g = lane >> 2, tq = lane & 3;
    int wr = (BN == 128) ? (wid & 3) : wid;
    int wc = (BN == 128) ? (wid >> 2) : 0;
    int row0 = blockIdx.x * 128;

    float4 acc[MI][8];
#pragma unroll
    for (int mi = 0; mi < MI; mi++)
#pragma unroll
        for (int nt = 0; nt < 8; nt++) acc[mi][nt] = make_float4(0.f, 0.f, 0.f, 0.f);

    const unsigned* pa[MI][2];
#pragma unroll
    for (int mi = 0; mi < MI; mi++) {
        int rb = row0 + wr * RPW + mi * 16;
        pa[mi][0] = Af + (size_t)(rb + g) * 128 + tq * 2;
        pa[mi][1] = Af + (size_t)(rb + g + 8) * 128 + tq * 2;
    }
    const unsigned* pb = Wf + ((size_t)(wc * 8) * 16 * 32 + lane) * 2;

#pragma unroll
    for (int kb = 0; kb < 16; kb++) {
        uint2 au[MI], av[MI];
#pragma unroll
        for (int mi = 0; mi < MI; mi++) {
            au[mi] = *(const uint2*)(pa[mi][0] + kb * 8);
            av[mi] = *(const uint2*)(pa[mi][1] + kb * 8);
        }
#pragma unroll
        for (int nt = 0; nt < 8; nt++) {
            uint2 b = *(const uint2*)(pb + (nt * 16 + kb) * 64);
#pragma unroll
            for (int mi = 0; mi < MI; mi++)
                mma_k8(acc[mi][nt], au[mi].x, av[mi].x, au[mi].y, av[mi].y,
                       b.x, b.y);
        }
    }

    float s1l[MI], s2l[MI], s1h[MI], s2h[MI];
#pragma unroll
    for (int mi = 0; mi < MI; mi++) { s1l[mi]=s2l[mi]=s1h[mi]=s2h[mi]=0.f; }
#pragma unroll
    for (int mi = 0; mi < MI; mi++) {
        int rA = row0 + wr * RPW + mi * 16 + g;
#pragma unroll
        for (int nt = 0; nt < 8; nt++) {
            int c0 = wc * 64 + nt * 8 + 2 * tq;
            float w1 = as_[c0], w1b = as_[c0 + 1];
            float w2 = ad_[c0], w2b = ad_[c0 + 1];
            float4 c = acc[mi][nt];
            s1l[mi] += c.x * w1 + c.y * w1b;
            s2l[mi] += c.x * w2 + c.y * w2b;
            s1h[mi] += c.z * w1 + c.w * w1b;
            s2h[mi] += c.z * w2 + c.w * w2b;
            if (rA < M)
                *(__half2*)&H[(size_t)rA * BN + c0] = __floats2half2_rn(c.x, c.y);
            if (rA + 8 < M)
                *(__half2*)&H[(size_t)(rA + 8) * BN + c0] = __floats2half2_rn(c.z, c.w);
        }
    }
#pragma unroll
    for (int mi = 0; mi < MI; mi++) {
#pragma unroll
        for (int o = 1; o < 4; o <<= 1) {
            s1l[mi] += __shfl_xor_sync(0xffffffffu, s1l[mi], o);
            s2l[mi] += __shfl_xor_sync(0xffffffffu, s2l[mi], o);
            s1h[mi] += __shfl_xor_sync(0xffffffffu, s1h[mi], o);
            s2h[mi] += __shfl_xor_sync(0xffffffffu, s2h[mi], o);
        }
    }
    if (BN == 64) {
        if (tq == 0) {
            int rA = row0 + wr * RPW + g;
            if (rA < M)     { g_ss[rA] = s1l[0];     g_sd[rA] = s2l[0]; }
            if (rA + 8 < M) { g_ss[rA + 8] = s1h[0]; g_sd[rA + 8] = s2h[0]; }
        }
    } else {
        if (tq == 0) {
#pragma unroll
            for (int mi = 0; mi < MI; mi++) {
                int rib = wr * RPW + mi * 16 + g;
                Sp[wc * 128 + rib]           = s1l[mi];
                Sp[wc * 128 + rib + 8]       = s1h[mi];
                Sp[256 + wc * 128 + rib]     = s2l[mi];
                Sp[256 + wc * 128 + rib + 8] = s2h[mi];
            }
        }
        __syncthreads();
        if (tid < 128) {
            int r = row0 + tid;
            if (r < M) {
                g_ss[r] = Sp[tid] + Sp[128 + tid];
                g_sd[r] = Sp[256 + tid] + Sp[384 + tid];
            }
        }
    }
}

// ---------------------------------------------------------------------------
// Warp-per-dst online softmax + aggregation, packed CSR, folded self-loop.
__global__ void aggregate128(int layer, const float* __restrict__ bias,
                             unsigned* __restrict__ outf, int n) {
    int node = blockIdx.x * (blockDim.x >> 5) + (threadIdx.x >> 5);
    int lane = threadIdx.x & 31;
    if (node >= n) return;
    int e0 = g_off[node], e1 = g_off[node + 1];
    float sdn = g_sd[node];

    float m = -INFINITY, denom = 0.f, csum = 0.f;
    float4 acc = make_float4(0.f, 0.f, 0.f, 0.f);

    for (int jb = e0; jb < e1; jb += 32) {
        int j = jb + lane;
        float a = -INFINITY;
        int s = 0;
        if (j < e1) {
            int4 pe = g_csr[j];
            s = pe.x;
            float cv = __int_as_float(layer == 0 ? pe.y : (layer == 1 ? pe.z : pe.w));
            csum += cv;
            a = g_ss[s] + sdn + cv;
            a = (a > 0.f) ? a : 0.2f * a;
        }
        float bm = a;
#pragma unroll
        for (int o = 16; o; o >>= 1) bm = fmaxf(bm, __shfl_xor_sync(0xffffffffu, bm, o));
        float newm = fmaxf(m, bm);
        float scale = __expf(m - newm);
        denom *= scale;
        acc.x *= scale; acc.y *= scale; acc.z *= scale; acc.w *= scale;
        m = newm;
        float ex = (j < e1) ? __expf(a - m) : 0.f;
        denom += ex;
        int kmax = min(e1 - jb, 32);
        for (int k = 0; k < kmax; k += 8) {
            float ef[8]; int sv[8];
#pragma unroll
            for (int q = 0; q < 8; q++) {
                ef[q] = __shfl_sync(0xffffffffu, ex, k + q);
                sv[q] = __shfl_sync(0xffffffffu, s, k + q);
            }
            __half2 hv[8][2];
#pragma unroll
            for (int q = 0; q < 8; q++) {
                const __half2* hp = (const __half2*)(g_h + (size_t)sv[q] * 128) + lane * 2;
                hv[q][0] = hp[0]; hv[q][1] = hp[1];
            }
#pragma unroll
            for (int q = 0; q < 8; q++) {
                float2 lo = __half22float2(hv[q][0]);
                float2 hi = __half22float2(hv[q][1]);
                acc.x += ef[q] * lo.x; acc.y += ef[q] * lo.y;
                acc.z += ef[q] * hi.x; acc.w += ef[q] * hi.y;
            }
        }
    }
#pragma unroll
    for (int o = 16; o; o >>= 1) {
        csum  += __shfl_xor_sync(0xffffffffu, csum, o);
        denom += __shfl_xor_sync(0xffffffffu, denom, o);
    }
    float invd = 1.f / fmaxf((float)(e1 - e0), 1.f);
    float aself = g_ss[node] + sdn + csum * invd;
    aself = (aself > 0.f) ? aself : 0.2f * aself;
    float newm = fmaxf(m, aself);
    float scale = __expf(m - newm);
    float exs = __expf(aself - newm);
    denom = denom * scale + exs;
    acc.x *= scale; acc.y *= scale; acc.z *= scale; acc.w *= scale;
    {
        const __half2* hp = (const __half2*)(g_h + (size_t)node * 128) + lane * 2;
        float2 lo = __half22float2(hp[0]);
        float2 hi = __half22float2(hp[1]);
        acc.x += exs * lo.x; acc.y += exs * lo.y;
        acc.z += exs * hi.x; acc.w += exs * hi.y;
    }
    float inv = 1.f / (denom + 1e-16f);
    float4 b = *(const float4*)(bias + lane * 4);
    float4 r;
    r.x = fmaxf(acc.x * inv + b.x, 0.f);
    r.y = fmaxf(acc.y * inv + b.y, 0.f);
    r.z = fmaxf(acc.z * inv + b.z, 0.f);
    r.w = fmaxf(acc.w * inv + b.w, 0.f);
    unsigned* base = outf + (size_t)node * 128 + (lane >> 1) * 8 + (lane & 1);
    base[0] = f2tf32(r.x); base[2] = f2tf32(r.y);
    base[4] = f2tf32(r.z); base[6] = f2tf32(r.w);
}

__global__ void aggregate64(int layer, const float* __restrict__ bias,
                            float* __restrict__ out, int n) {
    int node = blockIdx.x * (blockDim.x >> 5) + (threadIdx.x >> 5);
    int lane = threadIdx.x & 31;
    if (node >= n) return;
    int e0 = g_off[node], e1 = g_off[node + 1];
    float sdn = g_sd[node];

    float m = -INFINITY, denom = 0.f, csum = 0.f;
    float2 acc = make_float2(0.f, 0.f);

    for (int jb = e0; jb < e1; jb += 32) {
        int j = jb + lane;
        float a = -INFINITY;
        int s = 0;
        if (j < e1) {
            int4 pe = g_csr[j];
            s = pe.x;
            float cv = __int_as_float(layer == 0 ? pe.y : (layer == 1 ? pe.z : pe.w));
            csum += cv;
            a = g_ss[s] + sdn + cv;
            a = (a > 0.f) ? a : 0.2f * a;
        }
        float bm = a;
#pragma unroll
        for (int o = 16; o; o >>= 1) bm = fmaxf(bm, __shfl_xor_sync(0xffffffffu, bm, o));
        float newm = fmaxf(m, bm);
        float scale = __expf(m - newm);
        denom *= scale;
        acc.x *= scale; acc.y *= scale;
        m = newm;
        float ex = (j < e1) ? __expf(a - m) : 0.f;
        denom += ex;
        int kmax = min(e1 - jb, 32);
        for (int k = 0; k < kmax; k += 8) {
            float ef[8]; int sv[8];
#pragma unroll
            for (int q = 0; q < 8; q++) {
                ef[q] = __shfl_sync(0xffffffffu, ex, k + q);
                sv[q] = __shfl_sync(0xffffffffu, s, k + q);
            }
            __half2 hv[8];
#pragma unroll
            for (int q = 0; q < 8; q++)
                hv[q] = *((const __half2*)(g_h + (size_t)sv[q] * 64) + lane);
#pragma unroll
            for (int q = 0; q < 8; q++) {
                float2 lo = __half22float2(hv[q]);
                acc.x += ef[q] * lo.x; acc.y += ef[q] * lo.y;
            }
        }
    }
#pragma unroll
    for (int o = 16; o; o >>= 1) {
        csum  += __shfl_xor_sync(0xffffffffu, csum, o);
        denom += __shfl_xor_sync(0xffffffffu, denom, o);
    }
    float invd = 1.f / fmaxf((float)(e1 - e0), 1.f);
    float aself = g_ss[node] + sdn + csum * invd;
    aself = (aself > 0.f) ? aself : 0.2f * aself;
    float newm = fmaxf(m, aself);
    float scale = __expf(m - newm);
    float exs = __expf(aself - newm);
    denom = denom * scale + exs;
    acc.x *= scale; acc.y *= scale;
    {
        float2 lo = __half22float2(*((const __half2*)(g_h + (size_t)node * 64) + lane));
        acc.x += exs * lo.x; acc.y += exs * lo.y;
    }
    float inv = 1.f / (denom + 1e-16f);
    float2 b = *(const float2*)(bias + lane * 2);
    float2 r;
    r.x = acc.x * inv + b.x;
    r.y = acc.y * inv + b.y;
    *(float2*)(out + (size_t)node * 64 + lane * 2) = r;
}

extern "C" void kernel_launch(void* const* d_in, const int* in_sizes, int n_in,
                              void* d_out, int out_size) {
    const float* x      = (const float*)d_in[0];
    const void*  ei     = d_in[1];
    const float* ea     = (const float*)d_in[2];
    const float* W[3]  = {(const float*)d_in[3],  (const float*)d_in[9],  (const float*)d_in[15]};
    const float* As_[3]= {(const float*)d_in[4],  (const float*)d_in[10], (const float*)d_in[16]};
    const float* Ad[3] = {(const float*)d_in[5],  (const float*)d_in[11], (const float*)d_in[17]};
    const float* We[3] = {(const float*)d_in[6],  (const float*)d_in[12], (const float*)d_in[18]};
    const float* Ae[3] = {(const float*)d_in[7],  (const float*)d_in[13], (const float*)d_in[19]};
    const float* Bb[3] = {(const float*)d_in[8],  (const float*)d_in[14], (const float*)d_in[20]};

    int N = in_sizes[0] / 128;
    int E = in_sizes[2] / 8;
    int forced = (in_sizes[1] == 4 * E) ? 1 : -1;

    static __half* h = nullptr;
    static unsigned *xf = nullptr, *bufAf = nullptr, *bufBf = nullptr;
    static unsigned *wf0 = nullptr, *wf1 = nullptr, *wf2 = nullptr;
    if (!h) {
        cudaGetSymbolAddress((void**)&h,     g_h);
        cudaGetSymbolAddress((void**)&xf,    g_xf);
        cudaGetSymbolAddress((void**)&bufAf, g_bufAf);
        cudaGetSymbolAddress((void**)&bufBf, g_bufBf);
        cudaGetSymbolAddress((void**)&wf0,   g_wf0);
        cudaGetSymbolAddress((void**)&wf1,   g_wf1);
        cudaGetSymbolAddress((void**)&wf2,   g_wf2);
    }

    int gb = (N + 127) / 128;
    int nb = (N + 7) / 8;

    xform_kernel<<<(N * 32 + 40960 + 255) / 256, 256>>>(x, W[0], W[1], W[2], N);
    init_kernel<<<(N + 255) / 256, 256>>>((const int*)ei, forced,
                                          We[0], Ae[0], We[1], Ae[1], We[2], Ae[2], N);
    count_kernel<<<(E + 255) / 256, 256>>>(ei, E, N);
    gemm_frag<128><<<gb, 256>>>(xf, wf0, As_[0], Ad[0], h, N);
    scan_kernel<<<1, 1024>>>(N);
    edgefill_kernel<<<(E + 255) / 256, 256>>>(ea, ei, E, N);
    aggregate128<<<nb, 256>>>(0, Bb[0], bufAf, N);
    gemm_frag<128><<<gb, 256>>>(bufAf, wf1, As_[1], Ad[1], h, N);
    aggregate128<<<nb, 256>>>(1, Bb[1], bufBf, N);
    gemm_frag<64><<<gb, 256>>>(bufBf, wf2, As_[2], Ad[2], h, N);
    aggregate64<<<nb, 256>>>(2, Bb[2], (float*)d_out, N);
}

// round 12
// speedup vs baseline: 1.1481x; 1.0670x over previous
#include <cuda_runtime.h>
#include <cuda_fp16.h>
#include <math.h>

// ---------------------------------------------------------------------------
// GAT 3-layer pipeline. R12: paired-k frag layouts (LDG.128 operand loads in
// GEMM), no-max softmax aggregation, xform+init fused.
// Frag layout v2 (m16n8k8, k-pairs): element A[r][k] with kb=k>>3, j=(k>>2)&1,
// tq=k&3, p=kb>>1, o=kb&1 lives at word r*128 + p*16 + tq*4 + o*2 + j.
// W[k][n]: lane=(n&7)*4+(k&3), word ((n>>3)*8+p)*128 + lane*4 + o*2 + j.
// ---------------------------------------------------------------------------

#define MAXN 50048
#define MAXE 600064

__device__ __half   g_h[MAXN * 128];
__device__ unsigned g_xf[MAXN * 128];
__device__ unsigned g_bufAf[MAXN * 128];
__device__ unsigned g_bufBf[MAXN * 128];
__device__ unsigned g_wf0[16384];
__device__ unsigned g_wf1[16384];
__device__ unsigned g_wf2[8192];
__device__ float    g_ss[MAXN];
__device__ float    g_sd[MAXN];
__device__ int4     g_csr[MAXE];          // {src, cee0, cee1, cee2}
__device__ int      g_deg[MAXN];
__device__ int      g_off[MAXN + 1];
__device__ int      g_cur[MAXN];
__device__ float    g_v[24];
__device__ int      g_is64;

__device__ __forceinline__ int get_idx(const void* ei, int i) {
    if (g_is64) return (int)((const long long*)ei)[i];
    return ((const int*)ei)[i];
}

__device__ __forceinline__ unsigned f2tf32(float x) {
    unsigned u;
    asm("cvt.rna.tf32.f32 %0, %1;" : "=r"(u) : "f"(x));
    return u;
}

__device__ __forceinline__ void mma_k8(float4& c, unsigned a0, unsigned a1,
                                       unsigned a2, unsigned a3,
                                       unsigned b0, unsigned b1) {
    asm volatile(
        "mma.sync.aligned.m16n8k8.row.col.f32.tf32.tf32.f32 "
        "{%0,%1,%2,%3}, {%4,%5,%6,%7}, {%8,%9}, {%0,%1,%2,%3};"
        : "+f"(c.x), "+f"(c.y), "+f"(c.z), "+f"(c.w)
        : "r"(a0), "r"(a1), "r"(a2), "r"(a3), "r"(b0), "r"(b1));
}

// ---------------------------------------------------------------------------
// K1: x->frag, W->frag, deg zero, is64 detect, v vectors -- all fused.
__global__ void xform_init_kernel(const float* __restrict__ X,
                                  const float* __restrict__ W0,
                                  const float* __restrict__ W1,
                                  const float* __restrict__ W2,
                                  const int* __restrict__ eiw, int forced,
                                  const float* We0, const float* ae0,
                                  const float* We1, const float* ae1,
                                  const float* We2, const float* ae2,
                                  int M) {
    int f = blockIdx.x * blockDim.x + threadIdx.x;
    if (blockIdx.x == 0) {
        if (threadIdx.x == 0) {
            if (forced >= 0) g_is64 = forced;
            else {
                int is64 = 1;
                for (int j = 1; j < 32; j += 2)
                    if (eiw[j] != 0) is64 = 0;
                g_is64 = is64;
            }
        }
        int t = (int)threadIdx.x - 32;
        if (t >= 0 && t < 24) {
            int l = t / 8, j = t % 8;
            const float* We = (l == 0) ? We0 : (l == 1) ? We1 : We2;
            const float* ae = (l == 0) ? ae0 : (l == 1) ? ae1 : ae2;
            int C = (l == 2) ? 64 : 128;
            float s = 0.f;
            for (int c = 0; c < C; c++) s += We[j * C + c] * ae[c];
            g_v[l * 8 + j] = s;
        }
    }
    if (f < M * 32) {
        int r = f >> 5, c4 = (f & 31) << 2;
        float4 v = *(const float4*)(X + (size_t)r * 128 + c4);
        int kb = c4 >> 3, j = (c4 >> 2) & 1;
        // paired layout: base + tq*4
        unsigned* base = g_xf + (size_t)r * 128 + (kb >> 1) * 16 + (kb & 1) * 2 + j;
        base[0]  = f2tf32(v.x); base[4]  = f2tf32(v.y);
        base[8]  = f2tf32(v.z); base[12] = f2tf32(v.w);
        return;
    }
    int idx = f - M * 32;
    if (idx < 40960) {
        int l, e;
        if (idx < 16384)       { l = 0; e = idx; }
        else if (idx < 32768)  { l = 1; e = idx - 16384; }
        else                   { l = 2; e = idx - 32768; }
        int BN = (l == 2) ? 64 : 128;
        int k = e / BN, n = e % BN;
        const float* W = (l == 0) ? W0 : (l == 1) ? W1 : W2;
        unsigned* Wf = (l == 0) ? g_wf0 : (l == 1) ? g_wf1 : g_wf2;
        int lane = (n & 7) * 4 + (k & 3);
        int j = (k >> 2) & 1;
        int p = k >> 4, o = (k >> 3) & 1;
        int word = ((n >> 3) * 8 + p) * 128 + lane * 4 + o * 2 + j;
        Wf[word] = f2tf32(W[k * BN + n]);
        return;
    }
    int i2 = idx - 40960;
    if (i2 < MAXN) g_deg[i2] = 0;
}

__global__ void count_kernel(const void* __restrict__ ei, int E, int n) {
    int e = blockIdx.x * blockDim.x + threadIdx.x;
    if (e >= E) return;
    int d = get_idx(ei, E + e);
    if ((unsigned)d < (unsigned)n) atomicAdd(&g_deg[d], 1);
}

__global__ void scan_kernel(int n) {
    __shared__ int wsum[32];
    int tid = threadIdx.x;
    int per = (n + 1023) / 1024;
    int st = tid * per;
    int en = min(st + per, n);
    int s = 0;
    for (int i = st; i < en; i++) s += g_deg[i];
    int lane = tid & 31, wid = tid >> 5;
    int v = s;
#pragma unroll
    for (int o = 1; o < 32; o <<= 1) {
        int t = __shfl_up_sync(0xffffffffu, v, o);
        if (lane >= o) v += t;
    }
    if (lane == 31) wsum[wid] = v;
    __syncthreads();
    if (wid == 0) {
        int w = wsum[lane];
#pragma unroll
        for (int o = 1; o < 32; o <<= 1) {
            int t = __shfl_up_sync(0xffffffffu, w, o);
            if (lane >= o) w += t;
        }
        wsum[lane] = w;
    }
    __syncthreads();
    int base = v - s + ((wid > 0) ? wsum[wid - 1] : 0);
    for (int i = st; i < en; i++) {
        g_off[i] = base;
        g_cur[i] = base;
        base += g_deg[i];
    }
    if (tid == 1023) g_off[n] = base;
}

__global__ void edgefill_kernel(const float* __restrict__ ea,
                                const void* __restrict__ ei,
                                int E, int n) {
    int e = blockIdx.x * blockDim.x + threadIdx.x;
    if (e >= E) return;
    int s = get_idx(ei, e);
    int d = get_idx(ei, E + e);
    if ((unsigned)d >= (unsigned)n || (unsigned)s >= (unsigned)n) return;
    float a[8];
#pragma unroll
    for (int j = 0; j < 8; j++) a[j] = ea[e * 8 + j];
    float c[3];
#pragma unroll
    for (int l = 0; l < 3; l++) {
        float sv = 0.f;
#pragma unroll
        for (int j = 0; j < 8; j++) sv += a[j] * g_v[l * 8 + j];
        c[l] = sv;
    }
    int p = atomicAdd(&g_cur[d], 1);
    if (p >= MAXE) return;
    g_csr[p] = make_int4(s, __float_as_int(c[0]), __float_as_int(c[1]),
                         __float_as_int(c[2]));
}

// ---------------------------------------------------------------------------
// Smem-free tf32 GEMM, paired-k layout: LDG.128 operand loads.
template <int BN>
__global__ void __launch_bounds__(256, 2)
gemm_frag(const unsigned* __restrict__ Af, const unsigned* __restrict__ Wf,
          const float* __restrict__ as_, const float* __restrict__ ad_,
          __half* __restrict__ H, int M) {
    const int MI = (BN == 128) ? 2 : 1;
    const int RPW = (BN == 128) ? 32 : 16;
    __shared__ float Sp[512];
    int tid = threadIdx.x;
    int lane = tid & 31, wid = tid >> 5;
    int g = lane >> 2, tq = lane & 3;
    int wr = (BN == 128) ? (wid & 3) : wid;
    int wc = (BN == 128) ? (wid >> 2) : 0;
    int row0 = blockIdx.x * 128;

    float4 acc[MI][8];
#pragma unroll
    for (int mi = 0; mi < MI; mi++)
#pragma unroll
        for (int nt = 0; nt < 8; nt++) acc[mi][nt] = make_float4(0.f, 0.f, 0.f, 0.f);

    const unsigned* pa[MI][2];
#pragma unroll
    for (int mi = 0; mi < MI; mi++) {
        int rb = row0 + wr * RPW + mi * 16;
        pa[mi][0] = Af + (size_t)(rb + g) * 128 + tq * 4;
        pa[mi][1] = Af + (size_t)(rb + g + 8) * 128 + tq * 4;
    }
    const unsigned* pb = Wf + (size_t)(wc * 64) * 128 + lane * 4;

#pragma unroll
    for (int p = 0; p < 8; p++) {
        uint4 qa[MI], qb[MI];
#pragma unroll
        for (int mi = 0; mi < MI; mi++) {
            qa[mi] = *(const uint4*)(pa[mi][0] + p * 16);
            qb[mi] = *(const uint4*)(pa[mi][1] + p * 16);
        }
#pragma unroll
        for (int nt = 0; nt < 8; nt++) {
            uint4 w = *(const uint4*)(pb + (nt * 8 + p) * 128);
#pragma unroll
            for (int mi = 0; mi < MI; mi++) {
                mma_k8(acc[mi][nt], qa[mi].x, qb[mi].x, qa[mi].y, qb[mi].y,
                       w.x, w.y);
                mma_k8(acc[mi][nt], qa[mi].z, qb[mi].z, qa[mi].w, qb[mi].w,
                       w.z, w.w);
            }
        }
    }

    float s1l[MI], s2l[MI], s1h[MI], s2h[MI];
#pragma unroll
    for (int mi = 0; mi < MI; mi++) { s1l[mi]=s2l[mi]=s1h[mi]=s2h[mi]=0.f; }
#pragma unroll
    for (int mi = 0; mi < MI; mi++) {
        int rA = row0 + wr * RPW + mi * 16 + g;
#pragma unroll
        for (int nt = 0; nt < 8; nt++) {
            int c0 = wc * 64 + nt * 8 + 2 * tq;
            float w1 = as_[c0], w1b = as_[c0 + 1];
            float w2 = ad_[c0], w2b = ad_[c0 + 1];
            float4 c = acc[mi][nt];
            s1l[mi] += c.x * w1 + c.y * w1b;
            s2l[mi] += c.x * w2 + c.y * w2b;
            s1h[mi] += c.z * w1 + c.w * w1b;
            s2h[mi] += c.z * w2 + c.w * w2b;
            if (rA < M)
                *(__half2*)&H[(size_t)rA * BN + c0] = __floats2half2_rn(c.x, c.y);
            if (rA + 8 < M)
                *(__half2*)&H[(size_t)(rA + 8) * BN + c0] = __floats2half2_rn(c.z, c.w);
        }
    }
#pragma unroll
    for (int mi = 0; mi < MI; mi++) {
#pragma unroll
        for (int o = 1; o < 4; o <<= 1) {
            s1l[mi] += __shfl_xor_sync(0xffffffffu, s1l[mi], o);
            s2l[mi] += __shfl_xor_sync(0xffffffffu, s2l[mi], o);
            s1h[mi] += __shfl_xor_sync(0xffffffffu, s1h[mi], o);
            s2h[mi] += __shfl_xor_sync(0xffffffffu, s2h[mi], o);
        }
    }
    if (BN == 64) {
        if (tq == 0) {
            int rA = row0 + wr * RPW + g;
            if (rA < M)     { g_ss[rA] = s1l[0];     g_sd[rA] = s2l[0]; }
            if (rA + 8 < M) { g_ss[rA + 8] = s1h[0]; g_sd[rA + 8] = s2h[0]; }
        }
    } else {
        if (tq == 0) {
#pragma unroll
            for (int mi = 0; mi < MI; mi++) {
                int rib = wr * RPW + mi * 16 + g;
                Sp[wc * 128 + rib]           = s1l[mi];
                Sp[wc * 128 + rib + 8]       = s1h[mi];
                Sp[256 + wc * 128 + rib]     = s2l[mi];
                Sp[256 + wc * 128 + rib + 8] = s2h[mi];
            }
        }
        __syncthreads();
        if (tid < 128) {
            int r = row0 + tid;
            if (r < M) {
                g_ss[r] = Sp[tid] + Sp[128 + tid];
                g_sd[r] = Sp[256 + tid] + Sp[384 + tid];
            }
        }
    }
}

// ---------------------------------------------------------------------------
// Warp-per-dst aggregation, packed CSR, folded self-loop, NO-MAX softmax
// (scores are O(1)-bounded; exp never overflows; ratio identical to reference).
__global__ void aggregate128(int layer, const float* __restrict__ bias,
                             unsigned* __restrict__ outf, int n) {
    int node = blockIdx.x * (blockDim.x >> 5) + (threadIdx.x >> 5);
    int lane = threadIdx.x & 31;
    if (node >= n) return;
    int e0 = g_off[node], e1 = g_off[node + 1];
    float sdn = g_sd[node];

    float denom = 0.f, csum = 0.f;
    float4 acc = make_float4(0.f, 0.f, 0.f, 0.f);

    for (int jb = e0; jb < e1; jb += 32) {
        int j = jb + lane;
        float ex = 0.f;
        int s = 0;
        if (j < e1) {
            int4 pe = g_csr[j];
            s = pe.x;
            float cv = __int_as_float(layer == 0 ? pe.y : (layer == 1 ? pe.z : pe.w));
            csum += cv;
            float a = g_ss[s] + sdn + cv;
            a = (a > 0.f) ? a : 0.2f * a;
            ex = __expf(a);
            denom += ex;
        }
        int kmax = min(e1 - jb, 32);
        for (int k = 0; k < kmax; k += 8) {
            float ef[8]; int sv[8];
#pragma unroll
            for (int q = 0; q < 8; q++) {
                ef[q] = __shfl_sync(0xffffffffu, ex, k + q);
                sv[q] = __shfl_sync(0xffffffffu, s, k + q);
            }
            uint2 hv[8];
#pragma unroll
            for (int q = 0; q < 8; q++)
                hv[q] = *(const uint2*)((const __half2*)(g_h + (size_t)sv[q] * 128) + lane * 2);
#pragma unroll
            for (int q = 0; q < 8; q++) {
                float2 lo = __half22float2(*(const __half2*)&hv[q].x);
                float2 hi = __half22float2(*(const __half2*)&hv[q].y);
                acc.x += ef[q] * lo.x; acc.y += ef[q] * lo.y;
                acc.z += ef[q] * hi.x; acc.w += ef[q] * hi.y;
            }
        }
    }
#pragma unroll
    for (int o = 16; o; o >>= 1) {
        csum  += __shfl_xor_sync(0xffffffffu, csum, o);
        denom += __shfl_xor_sync(0xffffffffu, denom, o);
    }
    float invd = 1.f / fmaxf((float)(e1 - e0), 1.f);
    float aself = g_ss[node] + sdn + csum * invd;
    aself = (aself > 0.f) ? aself : 0.2f * aself;
    float exs = __expf(aself);
    denom += exs;
    {
        const __half2* hp = (const __half2*)(g_h + (size_t)node * 128) + lane * 2;
        float2 lo = __half22float2(hp[0]);
        float2 hi = __half22float2(hp[1]);
        acc.x += exs * lo.x; acc.y += exs * lo.y;
        acc.z += exs * hi.x; acc.w += exs * hi.y;
    }
    float inv = 1.f / (denom + 1e-16f);
    float4 b = *(const float4*)(bias + lane * 4);
    float4 r;
    r.x = fmaxf(acc.x * inv + b.x, 0.f);
    r.y = fmaxf(acc.y * inv + b.y, 0.f);
    r.z = fmaxf(acc.z * inv + b.z, 0.f);
    r.w = fmaxf(acc.w * inv + b.w, 0.f);
    // paired frag-layout store: lane holds cols 4*lane..4*lane+3
    unsigned* base = outf + (size_t)node * 128 + (lane >> 2) * 16 +
                     ((lane >> 1) & 1) * 2 + (lane & 1);
    base[0]  = f2tf32(r.x); base[4]  = f2tf32(r.y);
    base[8]  = f2tf32(r.z); base[12] = f2tf32(r.w);
}

__global__ void aggregate64(int layer, const float* __restrict__ bias,
                            float* __restrict__ out, int n) {
    int node = blockIdx.x * (blockDim.x >> 5) + (threadIdx.x >> 5);
    int lane = threadIdx.x & 31;
    if (node >= n) return;
    int e0 = g_off[node], e1 = g_off[node + 1];
    float sdn = g_sd[node];

    float denom = 0.f, csum = 0.f;
    float2 acc = make_float2(0.f, 0.f);

    for (int jb = e0; jb < e1; jb += 32) {
        int j = jb + lane;
        float ex = 0.f;
        int s = 0;
        if (j < e1) {
            int4 pe = g_csr[j];
            s = pe.x;
            float cv = __int_as_float(layer == 0 ? pe.y : (layer == 1 ? pe.z : pe.w));
            csum += cv;
            float a = g_ss[s] + sdn + cv;
            a = (a > 0.f) ? a : 0.2f * a;
            ex = __expf(a);
            denom += ex;
        }
        int kmax = min(e1 - jb, 32);
        for (int k = 0; k < kmax; k += 8) {
            float ef[8]; int sv[8];
#pragma unroll
            for (int q = 0; q < 8; q++) {
                ef[q] = __shfl_sync(0xffffffffu, ex, k + q);
                sv[q] = __shfl_sync(0xffffffffu, s, k + q);
            }
            __half2 hv[8];
#pragma unroll
            for (int q = 0; q < 8; q++)
                hv[q] = *((const __half2*)(g_h + (size_t)sv[q] * 64) + lane);
#pragma unroll
            for (int q = 0; q < 8; q++) {
                float2 lo = __half22float2(hv[q]);
                acc.x += ef[q] * lo.x; acc.y += ef[q] * lo.y;
            }
        }
    }
#pragma unroll
    for (int o = 16; o; o >>= 1) {
        csum  += __shfl_xor_sync(0xffffffffu, csum, o);
        denom += __shfl_xor_sync(0xffffffffu, denom, o);
    }
    float invd = 1.f / fmaxf((float)(e1 - e0), 1.f);
    float aself = g_ss[node] + sdn + csum * invd;
    aself = (aself > 0.f) ? aself : 0.2f * aself;
    float exs = __expf(aself);
    denom += exs;
    {
        float2 lo = __half22float2(*((const __half2*)(g_h + (size_t)node * 64) + lane));
        acc.x += exs * lo.x; acc.y += exs * lo.y;
    }
    float inv = 1.f / (denom + 1e-16f);
    float2 b = *(const float2*)(bias + lane * 2);
    float2 r;
    r.x = acc.x * inv + b.x;
    r.y = acc.y * inv + b.y;
    *(float2*)(out + (size_t)node * 64 + lane * 2) = r;
}

extern "C" void kernel_launch(void* const* d_in, const int* in_sizes, int n_in,
                              void* d_out, int out_size) {
    const float* x      = (const float*)d_in[0];
    const void*  ei     = d_in[1];
    const float* ea     = (const float*)d_in[2];
    const float* W[3]  = {(const float*)d_in[3],  (const float*)d_in[9],  (const float*)d_in[15]};
    const float* As_[3]= {(const float*)d_in[4],  (const float*)d_in[10], (const float*)d_in[16]};
    const float* Ad[3] = {(const float*)d_in[5],  (const float*)d_in[11], (const float*)d_in[17]};
    const float* We[3] = {(const float*)d_in[6],  (const float*)d_in[12], (const float*)d_in[18]};
    const float* Ae[3] = {(const float*)d_in[7],  (const float*)d_in[13], (const float*)d_in[19]};
    const float* Bb[3] = {(const float*)d_in[8],  (const float*)d_in[14], (const float*)d_in[20]};

    int N = in_sizes[0] / 128;
    int E = in_sizes[2] / 8;
    int forced = (in_sizes[1] == 4 * E) ? 1 : -1;

    static __half* h = nullptr;
    static unsigned *xf = nullptr, *bufAf = nullptr, *bufBf = nullptr;
    static unsigned *wf0 = nullptr, *wf1 = nullptr, *wf2 = nullptr;
    if (!h) {
        cudaGetSymbolAddress((void**)&h,     g_h);
        cudaGetSymbolAddress((void**)&xf,    g_xf);
        cudaGetSymbolAddress((void**)&bufAf, g_bufAf);
        cudaGetSymbolAddress((void**)&bufBf, g_bufBf);
        cudaGetSymbolAddress((void**)&wf0,   g_wf0);
        cudaGetSymbolAddress((void**)&wf1,   g_wf1);
        cudaGetSymbolAddress((void**)&wf2,   g_wf2);
    }

    int gb = (N + 127) / 128;
    int nb = (N + 7) / 8;

    // 1: xform+init (fused); 2: count; 3: scan; 4: gemm0 (profiled slot)
    xform_init_kernel<<<(N * 32 + 40960 + MAXN + 255) / 256, 256>>>(
        x, W[0], W[1], W[2], (const int*)ei, forced,
        We[0], Ae[0], We[1], Ae[1], We[2], Ae[2], N);
    count_kernel<<<(E + 255) / 256, 256>>>(ei, E, N);
    scan_kernel<<<1, 1024>>>(N);
    gemm_frag<128><<<gb, 256>>>(xf, wf0, As_[0], Ad[0], h, N);
    edgefill_kernel<<<(E + 255) / 256, 256>>>(ea, ei, E, N);
    aggregate128<<<nb, 256>>>(0, Bb[0], bufAf, N);
    gemm_frag<128><<<gb, 256>>>(bufAf, wf1, As_[1], Ad[1], h, N);
    aggregate128<<<nb, 256>>>(1, Bb[1], bufBf, N);
    gemm_frag<64><<<gb, 256>>>(bufBf, wf2, As_[2], Ad[2], h, N);
    aggregate64<<<nb, 256>>>(2, Bb[2], (float*)d_out, N);
}

// round 13
// speedup vs baseline: 1.2488x; 1.0877x over previous
#include <cuda_runtime.h>
#include <cuda_fp16.h>
#include <math.h>

// ---------------------------------------------------------------------------
// GAT 3-layer pipeline. R13: fp16 m16n8k16 tensor-core GEMM (half the MMAs
// and half the operand traffic of tf32 k8), fp16 fragment layouts everywhere,
// gemm0+edgefill fused into one block-split launch.
// fp16 frag layout (m16n8k16): element A[r][k]: p=k>>5, o=(k>>4)&1, kk=k&15,
// i=(kk>=8), tq=(kk&7)>>1, hs=k&1 -> half idx r*128 + p*32+tq*8+o*4+i*2+hs.
// Lane (g=lane>>2,tq=lane&3) loads uint4 at b32word r*64 + p*16 + tq*4 =
// [kb0:a0/a2, kb1:a0/a2] for row r=g (and r=g+8 for a1/a3).
// W[k][n]: lane=(n&7)*4+tq; b32word ((n>>3)*4+p)*128 + lane*4 + o*2 + i.
// ---------------------------------------------------------------------------

#define MAXN 50048
#define MAXE 600064

__device__ __half   g_h[MAXN * 128];       // GEMM output, row-major (gathered)
__device__ __half   g_xf[MAXN * 128];      // x in fp16 frag layout
__device__ __half   g_bufAf[MAXN * 128];   // layer-0 out, fp16 frag layout
__device__ __half   g_bufBf[MAXN * 128];   // layer-1 out, fp16 frag layout
__device__ __half   g_wf0[16384];
__device__ __half   g_wf1[16384];
__device__ __half   g_wf2[8192];
__device__ float    g_ss[MAXN];
__device__ float    g_sd[MAXN];
__device__ int4     g_csr[MAXE];           // {src, cee0, cee1, cee2}
__device__ int      g_deg[MAXN];
__device__ int      g_off[MAXN + 1];
__device__ int      g_cur[MAXN];
__device__ float    g_v[24];
__device__ int      g_is64;

__device__ __forceinline__ int get_idx(const void* ei, int i) {
    if (g_is64) return (int)((const long long*)ei)[i];
    return ((const int*)ei)[i];
}

__device__ __forceinline__ void mma_f16(float4& c, unsigned a0, unsigned a1,
                                        unsigned a2, unsigned a3,
                                        unsigned b0, unsigned b1) {
    asm volatile(
        "mma.sync.aligned.m16n8k16.row.col.f32.f16.f16.f32 "
        "{%0,%1,%2,%3}, {%4,%5,%6,%7}, {%8,%9}, {%0,%1,%2,%3};"
        : "+f"(c.x), "+f"(c.y), "+f"(c.z), "+f"(c.w)
        : "r"(a0), "r"(a1), "r"(a2), "r"(a3), "r"(b0), "r"(b1));
}

// ---------------------------------------------------------------------------
// K1: x->fp16 frag, W->fp16 frag, deg zero, is64 detect, v vectors (fused).
__global__ void xform_init_kernel(const float* __restrict__ X,
                                  const float* __restrict__ W0,
                                  const float* __restrict__ W1,
                                  const float* __restrict__ W2,
                                  const int* __restrict__ eiw, int forced,
                                  const float* We0, const float* ae0,
                                  const float* We1, const float* ae1,
                                  const float* We2, const float* ae2,
                                  int M) {
    int f = blockIdx.x * blockDim.x + threadIdx.x;
    if (blockIdx.x == 0) {
        if (threadIdx.x == 0) {
            if (forced >= 0) g_is64 = forced;
            else {
                int is64 = 1;
                for (int j = 1; j < 32; j += 2)
                    if (eiw[j] != 0) is64 = 0;
                g_is64 = is64;
            }
        }
        int t = (int)threadIdx.x - 32;
        if (t >= 0 && t < 24) {
            int l = t / 8, j = t % 8;
            const float* We = (l == 0) ? We0 : (l == 1) ? We1 : We2;
            const float* ae = (l == 0) ? ae0 : (l == 1) ? ae1 : ae2;
            int C = (l == 2) ? 64 : 128;
            float s = 0.f;
            for (int c = 0; c < C; c++) s += We[j * C + c] * ae[c];
            g_v[l * 8 + j] = s;
        }
    }
    if (f < M * 32) {
        int r = f >> 5;
        int k0 = (f & 31) << 2;
        float4 v = *(const float4*)(X + (size_t)r * 128 + k0);
        int p = k0 >> 5, o = (k0 >> 4) & 1, kk = k0 & 15;
        int i = (kk >= 8) ? 1 : 0;
        int tq = (kk & 7) >> 1;
        int hb = p * 32 + tq * 8 + o * 4 + i * 2;   // even
        __half2* hp = (__half2*)(g_xf + (size_t)r * 128);
        hp[hb >> 1]       = __floats2half2_rn(v.x, v.y);
        hp[(hb >> 1) + 4] = __floats2half2_rn(v.z, v.w);
        return;
    }
    int idx = f - M * 32;
    if (idx < 40960) {
        int l, e;
        if (idx < 16384)       { l = 0; e = idx; }
        else if (idx < 32768)  { l = 1; e = idx - 16384; }
        else                   { l = 2; e = idx - 32768; }
        int BN = (l == 2) ? 64 : 128;
        int k = e / BN, n = e % BN;
        const float* W = (l == 0) ? W0 : (l == 1) ? W1 : W2;
        __half* Wf = (l == 0) ? g_wf0 : (l == 1) ? g_wf1 : g_wf2;
        int p = k >> 5, o = (k >> 4) & 1, kk = k & 15;
        int i = (kk >= 8) ? 1 : 0;
        int tq = (kk & 7) >> 1, hs = k & 1;
        int lane = (n & 7) * 4 + tq;
        int word = ((n >> 3) * 4 + p) * 128 + lane * 4 + o * 2 + i;
        Wf[word * 2 + hs] = __float2half(W[k * BN + n]);
        return;
    }
    int i2 = idx - 40960;
    if (i2 < MAXN) g_deg[i2] = 0;
}

__global__ void count_kernel(const void* __restrict__ ei, int E, int n) {
    int e = blockIdx.x * blockDim.x + threadIdx.x;
    if (e >= E) return;
    int d = get_idx(ei, E + e);
    if ((unsigned)d < (unsigned)n) atomicAdd(&g_deg[d], 1);
}

__global__ void scan_kernel(int n) {
    __shared__ int wsum[32];
    int tid = threadIdx.x;
    int per = (n + 1023) / 1024;
    int st = tid * per;
    int en = min(st + per, n);
    int s = 0;
    for (int i = st; i < en; i++) s += g_deg[i];
    int lane = tid & 31, wid = tid >> 5;
    int v = s;
#pragma unroll
    for (int o = 1; o < 32; o <<= 1) {
        int t = __shfl_up_sync(0xffffffffu, v, o);
        if (lane >= o) v += t;
    }
    if (lane == 31) wsum[wid] = v;
    __syncthreads();
    if (wid == 0) {
        int w = wsum[lane];
#pragma unroll
        for (int o = 1; o < 32; o <<= 1) {
            int t = __shfl_up_sync(0xffffffffu, w, o);
            if (lane >= o) w += t;
        }
        wsum[lane] = w;
    }
    __syncthreads();
    int base = v - s + ((wid > 0) ? wsum[wid - 1] : 0);
    for (int i = st; i < en; i++) {
        g_off[i] = base;
        g_cur[i] = base;
        base += g_deg[i];
    }
    if (tid == 1023) g_off[n] = base;
}

// ---------------------------------------------------------------------------
__device__ __forceinline__ void edgefill_body(const float* __restrict__ ea,
                                              const void* __restrict__ ei,
                                              int e, int E, int n) {
    if (e >= E) return;
    int s = get_idx(ei, e);
    int d = get_idx(ei, E + e);
    if ((unsigned)d >= (unsigned)n || (unsigned)s >= (unsigned)n) return;
    float a[8];
#pragma unroll
    for (int j = 0; j < 8; j++) a[j] = ea[e * 8 + j];
    float c[3];
#pragma unroll
    for (int l = 0; l < 3; l++) {
        float sv = 0.f;
#pragma unroll
        for (int j = 0; j < 8; j++) sv += a[j] * g_v[l * 8 + j];
        c[l] = sv;
    }
    int p = atomicAdd(&g_cur[d], 1);
    if (p >= MAXE) return;
    g_csr[p] = make_int4(s, __float_as_int(c[0]), __float_as_int(c[1]),
                         __float_as_int(c[2]));
}

// ---------------------------------------------------------------------------
// Smem-free fp16 GEMM body (m16n8k16). BM=128; BN=128: warps 4x2, tile 32x64;
// BN=64: 8x1, tile 16x64. H stored row-major fp16; fused scores.
template <int BN>
__device__ __forceinline__ void gemm_body(const __half* __restrict__ Af,
                                          const __half* __restrict__ Wf,
                                          const float* __restrict__ as_,
                                          const float* __restrict__ ad_,
                                          __half* __restrict__ H, int M,
                                          int bid) {
    const int MI = (BN == 128) ? 2 : 1;
    const int RPW = (BN == 128) ? 32 : 16;
    __shared__ float Sp[512];
    int tid = threadIdx.x;
    int lane = tid & 31, wid = tid >> 5;
    int g = lane >> 2, tq = lane & 3;
    int wr = (BN == 128) ? (wid & 3) : wid;
    int wc = (BN == 128) ? (wid >> 2) : 0;
    int row0 = bid * 128;

    float4 acc[MI][8];
#pragma unroll
    for (int mi = 0; mi < MI; mi++)
#pragma unroll
        for (int nt = 0; nt < 8; nt++) acc[mi][nt] = make_float4(0.f, 0.f, 0.f, 0.f);

    const uint4* pa[MI][2];
#pragma unroll
    for (int mi = 0; mi < MI; mi++) {
        int rb = row0 + wr * RPW + mi * 16;
        pa[mi][0] = (const uint4*)Af + (size_t)(rb + g) * 16 + tq;
        pa[mi][1] = (const uint4*)Af + (size_t)(rb + g + 8) * 16 + tq;
    }
    const uint4* pb = (const uint4*)Wf + (size_t)(wc * 8 * 4) * 32 + lane;

#pragma unroll
    for (int p = 0; p < 4; p++) {
        uint4 qa[MI], qb[MI];
#pragma unroll
        for (int mi = 0; mi < MI; mi++) {
            qa[mi] = pa[mi][0][p * 4];
            qb[mi] = pa[mi][1][p * 4];
        }
#pragma unroll
        for (int nt = 0; nt < 8; nt++) {
            uint4 w = pb[(nt * 4 + p) * 32];
#pragma unroll
            for (int mi = 0; mi < MI; mi++) {
                mma_f16(acc[mi][nt], qa[mi].x, qb[mi].x, qa[mi].y, qb[mi].y,
                        w.x, w.y);
                mma_f16(acc[mi][nt], qa[mi].z, qb[mi].z, qa[mi].w, qb[mi].w,
                        w.z, w.w);
            }
        }
    }

    float s1l[MI], s2l[MI], s1h[MI], s2h[MI];
#pragma unroll
    for (int mi = 0; mi < MI; mi++) { s1l[mi]=s2l[mi]=s1h[mi]=s2h[mi]=0.f; }
#pragma unroll
    for (int mi = 0; mi < MI; mi++) {
        int rA = row0 + wr * RPW + mi * 16 + g;
#pragma unroll
        for (int nt = 0; nt < 8; nt++) {
            int c0 = wc * 64 + nt * 8 + 2 * tq;
            float w1 = as_[c0], w1b = as_[c0 + 1];
            float w2 = ad_[c0], w2b = ad_[c0 + 1];
            float4 c = acc[mi][nt];
            s1l[mi] += c.x * w1 + c.y * w1b;
            s2l[mi] += c.x * w2 + c.y * w2b;
            s1h[mi] += c.z * w1 + c.w * w1b;
            s2h[mi] += c.z * w2 + c.w * w2b;
            if (rA < M)
                *(__half2*)&H[(size_t)rA * BN + c0] = __floats2half2_rn(c.x, c.y);
            if (rA + 8 < M)
                *(__half2*)&H[(size_t)(rA + 8) * BN + c0] = __floats2half2_rn(c.z, c.w);
        }
    }
#pragma unroll
    for (int mi = 0; mi < MI; mi++) {
#pragma unroll
        for (int o = 1; o < 4; o <<= 1) {
            s1l[mi] += __shfl_xor_sync(0xffffffffu, s1l[mi], o);
            s2l[mi] += __shfl_xor_sync(0xffffffffu, s2l[mi], o);
            s1h[mi] += __shfl_xor_sync(0xffffffffu, s1h[mi], o);
            s2h[mi] += __shfl_xor_sync(0xffffffffu, s2h[mi], o);
        }
    }
    if (BN == 64) {
        if (tq == 0) {
            int rA = row0 + wr * RPW + g;
            if (rA < M)     { g_ss[rA] = s1l[0];     g_sd[rA] = s2l[0]; }
            if (rA + 8 < M) { g_ss[rA + 8] = s1h[0]; g_sd[rA + 8] = s2h[0]; }
        }
    } else {
        if (tq == 0) {
#pragma unroll
            for (int mi = 0; mi < MI; mi++) {
                int rib = wr * RPW + mi * 16 + g;
                Sp[wc * 128 + rib]           = s1l[mi];
                Sp[wc * 128 + rib + 8]       = s1h[mi];
                Sp[256 + wc * 128 + rib]     = s2l[mi];
                Sp[256 + wc * 128 + rib + 8] = s2h[mi];
            }
        }
        __syncthreads();
        if (tid < 128) {
            int r = row0 + tid;
            if (r < M) {
                g_ss[r] = Sp[tid] + Sp[128 + tid];
                g_sd[r] = Sp[256 + tid] + Sp[384 + tid];
            }
        }
    }
}

template <int BN>
__global__ void __launch_bounds__(256, 2)
gemm_frag(const __half* __restrict__ Af, const __half* __restrict__ Wf,
          const float* __restrict__ as_, const float* __restrict__ ad_,
          __half* __restrict__ H, int M) {
    gemm_body<BN>(Af, Wf, as_, ad_, H, M, blockIdx.x);
}

// Fused: first gb blocks run gemm0; rest run edgefill (independent work).
__global__ void __launch_bounds__(256, 2)
gemm0_edgefill(const __half* __restrict__ Af, const __half* __restrict__ Wf,
               const float* __restrict__ as_, const float* __restrict__ ad_,
               __half* __restrict__ H, int M, int gb,
               const float* __restrict__ ea, const void* __restrict__ ei,
               int E, int n) {
    if ((int)blockIdx.x < gb) {
        gemm_body<128>(Af, Wf, as_, ad_, H, M, blockIdx.x);
    } else {
        int e = (blockIdx.x - gb) * 256 + threadIdx.x;
        edgefill_body(ea, ei, e, E, n);
    }
}

// ---------------------------------------------------------------------------
// Warp-per-dst aggregation, packed CSR, folded self-loop, no-max softmax.
__global__ void aggregate128(int layer, const float* __restrict__ bias,
                             __half* __restrict__ outf, int n) {
    int node = blockIdx.x * (blockDim.x >> 5) + (threadIdx.x >> 5);
    int lane = threadIdx.x & 31;
    if (node >= n) return;
    int e0 = g_off[node], e1 = g_off[node + 1];
    float sdn = g_sd[node];

    float denom = 0.f, csum = 0.f;
    float4 acc = make_float4(0.f, 0.f, 0.f, 0.f);

    for (int jb = e0; jb < e1; jb += 32) {
        int j = jb + lane;
        float ex = 0.f;
        int s = 0;
        if (j < e1) {
            int4 pe = g_csr[j];
            s = pe.x;
            float cv = __int_as_float(layer == 0 ? pe.y : (layer == 1 ? pe.z : pe.w));
            csum += cv;
            float a = g_ss[s] + sdn + cv;
            a = (a > 0.f) ? a : 0.2f * a;
            ex = __expf(a);
            denom += ex;
        }
        int kmax = min(e1 - jb, 32);
        for (int k = 0; k < kmax; k += 8) {
            float ef[8]; int sv[8];
#pragma unroll
            for (int q = 0; q < 8; q++) {
                ef[q] = __shfl_sync(0xffffffffu, ex, k + q);
                sv[q] = __shfl_sync(0xffffffffu, s, k + q);
            }
            uint2 hv[8];
#pragma unroll
            for (int q = 0; q < 8; q++)
                hv[q] = *(const uint2*)((const __half2*)(g_h + (size_t)sv[q] * 128) + lane * 2);
#pragma unroll
            for (int q = 0; q < 8; q++) {
                float2 lo = __half22float2(*(const __half2*)&hv[q].x);
                float2 hi = __half22float2(*(const __half2*)&hv[q].y);
                acc.x += ef[q] * lo.x; acc.y += ef[q] * lo.y;
                acc.z += ef[q] * hi.x; acc.w += ef[q] * hi.y;
            }
        }
    }
#pragma unroll
    for (int o = 16; o; o >>= 1) {
        csum  += __shfl_xor_sync(0xffffffffu, csum, o);
        denom += __shfl_xor_sync(0xffffffffu, denom, o);
    }
    float invd = 1.f / fmaxf((float)(e1 - e0), 1.f);
    float aself = g_ss[node] + sdn + csum * invd;
    aself = (aself > 0.f) ? aself : 0.2f * aself;
    float exs = __expf(aself);
    denom += exs;
    {
        const __half2* hp = (const __half2*)(g_h + (size_t)node * 128) + lane * 2;
        float2 lo = __half22float2(hp[0]);
        float2 hi = __half22float2(hp[1]);
        acc.x += exs * lo.x; acc.y += exs * lo.y;
        acc.z += exs * hi.x; acc.w += exs * hi.y;
    }
    float inv = 1.f / (denom + 1e-16f);
    float4 b = *(const float4*)(bias + lane * 4);
    float4 r;
    r.x = fmaxf(acc.x * inv + b.x, 0.f);
    r.y = fmaxf(acc.y * inv + b.y, 0.f);
    r.z = fmaxf(acc.z * inv + b.z, 0.f);
    r.w = fmaxf(acc.w * inv + b.w, 0.f);
    // fp16 frag-layout store: lane owns cols 4l..4l+3
    __half2* op = (__half2*)(outf + (size_t)node * 128);
    int w0 = (lane >> 3) * 16 + (lane & 1) * 8 + ((lane >> 2) & 1) * 2 + ((lane >> 1) & 1);
    op[w0]     = __floats2half2_rn(r.x, r.y);
    op[w0 + 4] = __floats2half2_rn(r.z, r.w);
}

__global__ void aggregate64(int layer, const float* __restrict__ bias,
                            float* __restrict__ out, int n) {
    int node = blockIdx.x * (blockDim.x >> 5) + (threadIdx.x >> 5);
    int lane = threadIdx.x & 31;
    if (node >= n) return;
    int e0 = g_off[node], e1 = g_off[node + 1];
    float sdn = g_sd[node];

    float denom = 0.f, csum = 0.f;
    float2 acc = make_float2(0.f, 0.f);

    for (int jb = e0; jb < e1; jb += 32) {
        int j = jb + lane;
        float ex = 0.f;
        int s = 0;
        if (j < e1) {
            int4 pe = g_csr[j];
            s = pe.x;
            float cv = __int_as_float(layer == 0 ? pe.y : (layer == 1 ? pe.z : pe.w));
            csum += cv;
            float a = g_ss[s] + sdn + cv;
            a = (a > 0.f) ? a : 0.2f * a;
            ex = __expf(a);
            denom += ex;
        }
        int kmax = min(e1 - jb, 32);
        for (int k = 0; k < kmax; k += 8) {
            float ef[8]; int sv[8];
#pragma unroll
            for (int q = 0; q < 8; q++) {
                ef[q] = __shfl_sync(0xffffffffu, ex, k + q);
                sv[q] = __shfl_sync(0xffffffffu, s, k + q);
            }
            __half2 hv[8];
#pragma unroll
            for (int q = 0; q < 8; q++)
                hv[q] = *((const __half2*)(g_h + (size_t)sv[q] * 64) + lane);
#pragma unroll
            for (int q = 0; q < 8; q++) {
                float2 lo = __half22float2(hv[q]);
                acc.x += ef[q] * lo.x; acc.y += ef[q] * lo.y;
            }
        }
    }
#pragma unroll
    for (int o = 16; o; o >>= 1) {
        csum  += __shfl_xor_sync(0xffffffffu, csum, o);
        denom += __shfl_xor_sync(0xffffffffu, denom, o);
    }
    float invd = 1.f / fmaxf((float)(e1 - e0), 1.f);
    float aself = g_ss[node] + sdn + csum * invd;
    aself = (aself > 0.f) ? aself : 0.2f * aself;
    float exs = __expf(aself);
    denom += exs;
    {
        float2 lo = __half22float2(*((const __half2*)(g_h + (size_t)node * 64) + lane));
        acc.x += exs * lo.x; acc.y += exs * lo.y;
    }
    float inv = 1.f / (denom + 1e-16f);
    float2 b = *(const float2*)(bias + lane * 2);
    float2 r;
    r.x = acc.x * inv + b.x;
    r.y = acc.y * inv + b.y;
    *(float2*)(out + (size_t)node * 64 + lane * 2) = r;
}

extern "C" void kernel_launch(void* const* d_in, const int* in_sizes, int n_in,
                              void* d_out, int out_size) {
    const float* x      = (const float*)d_in[0];
    const void*  ei     = d_in[1];
    const float* ea     = (const float*)d_in[2];
    const float* W[3]  = {(const float*)d_in[3],  (const float*)d_in[9],  (const float*)d_in[15]};
    const float* As_[3]= {(const float*)d_in[4],  (const float*)d_in[10], (const float*)d_in[16]};
    const float* Ad[3] = {(const float*)d_in[5],  (const float*)d_in[11], (const float*)d_in[17]};
    const float* We[3] = {(const float*)d_in[6],  (const float*)d_in[12], (const float*)d_in[18]};
    const float* Ae[3] = {(const float*)d_in[7],  (const float*)d_in[13], (const float*)d_in[19]};
    const float* Bb[3] = {(const float*)d_in[8],  (const float*)d_in[14], (const float*)d_in[20]};

    int N = in_sizes[0] / 128;
    int E = in_sizes[2] / 8;
    int forced = (in_sizes[1] == 4 * E) ? 1 : -1;

    static __half* h = nullptr;
    static __half *xf = nullptr, *bufAf = nullptr, *bufBf = nullptr;
    static __half *wf0 = nullptr, *wf1 = nullptr, *wf2 = nullptr;
    if (!h) {
        cudaGetSymbolAddress((void**)&h,     g_h);
        cudaGetSymbolAddress((void**)&xf,    g_xf);
        cudaGetSymbolAddress((void**)&bufAf, g_bufAf);
        cudaGetSymbolAddress((void**)&bufBf, g_bufBf);
        cudaGetSymbolAddress((void**)&wf0,   g_wf0);
        cudaGetSymbolAddress((void**)&wf1,   g_wf1);
        cudaGetSymbolAddress((void**)&wf2,   g_wf2);
    }

    int gb = (N + 127) / 128;
    int nb = (N + 7) / 8;
    int eb = (E + 255) / 256;

    // 1: xform+init; 2: count; 3: scan; 4: gemm0 || edgefill (fused)
    xform_init_kernel<<<(N * 32 + 40960 + MAXN + 255) / 256, 256>>>(
        x, W[0], W[1], W[2], (const int*)ei, forced,
        We[0], Ae[0], We[1], Ae[1], We[2], Ae[2], N);
    count_kernel<<<eb, 256>>>(ei, E, N);
    scan_kernel<<<1, 1024>>>(N);
    gemm0_edgefill<<<gb + eb, 256>>>(xf, wf0, As_[0], Ad[0], h, N, gb,
                                     ea, ei, E, N);
    // 5-9: layers
    aggregate128<<<nb, 256>>>(0, Bb[0], bufAf, N);
    gemm_frag<128><<<gb, 256>>>(bufAf, wf1, As_[1], Ad[1], h, N);
    aggregate128<<<nb, 256>>>(1, Bb[1], bufBf, N);
    gemm_frag<64><<<gb, 256>>>(bufBf, wf2, As_[2], Ad[2], h, N);
    aggregate64<<<nb, 256>>>(2, Bb[2], (float*)d_out, N);
}

// round 14
// speedup vs baseline: 1.2695x; 1.0166x over previous
#include <cuda_runtime.h>
#include <cuda_fp16.h>
#include <math.h>

// ---------------------------------------------------------------------------
// GAT 3-layer pipeline. R14: split-warp aggregation (half-warp per edge,
// uint4 gathers) -- halves load+shuffle issue count in the dominant loop.
// fp16 m16n8k16 GEMM, fused launches, packed CSR, no-max softmax retained.
// ---------------------------------------------------------------------------

#define MAXN 50048
#define MAXE 600064

__device__ __half   g_h[MAXN * 128];
__device__ __half   g_xf[MAXN * 128];
__device__ __half   g_bufAf[MAXN * 128];
__device__ __half   g_bufBf[MAXN * 128];
__device__ __half   g_wf0[16384];
__device__ __half   g_wf1[16384];
__device__ __half   g_wf2[8192];
__device__ float    g_ss[MAXN];
__device__ float    g_sd[MAXN];
__device__ int4     g_csr[MAXE];
__device__ int      g_deg[MAXN];
__device__ int      g_off[MAXN + 1];
__device__ int      g_cur[MAXN];
__device__ float    g_v[24];
__device__ int      g_is64;

__device__ __forceinline__ int get_idx(const void* ei, int i) {
    if (g_is64) return (int)((const long long*)ei)[i];
    return ((const int*)ei)[i];
}

__device__ __forceinline__ void mma_f16(float4& c, unsigned a0, unsigned a1,
                                        unsigned a2, unsigned a3,
                                        unsigned b0, unsigned b1) {
    asm volatile(
        "mma.sync.aligned.m16n8k16.row.col.f32.f16.f16.f32 "
        "{%0,%1,%2,%3}, {%4,%5,%6,%7}, {%8,%9}, {%0,%1,%2,%3};"
        : "+f"(c.x), "+f"(c.y), "+f"(c.z), "+f"(c.w)
        : "r"(a0), "r"(a1), "r"(a2), "r"(a3), "r"(b0), "r"(b1));
}

// ---------------------------------------------------------------------------
__global__ void xform_init_kernel(const float* __restrict__ X,
                                  const float* __restrict__ W0,
                                  const float* __restrict__ W1,
                                  const float* __restrict__ W2,
                                  const int* __restrict__ eiw, int forced,
                                  const float* We0, const float* ae0,
                                  const float* We1, const float* ae1,
                                  const float* We2, const float* ae2,
                                  int M) {
    int f = blockIdx.x * blockDim.x + threadIdx.x;
    if (blockIdx.x == 0) {
        if (threadIdx.x == 0) {
            if (forced >= 0) g_is64 = forced;
            else {
                int is64 = 1;
                for (int j = 1; j < 32; j += 2)
                    if (eiw[j] != 0) is64 = 0;
                g_is64 = is64;
            }
        }
        int t = (int)threadIdx.x - 32;
        if (t >= 0 && t < 24) {
            int l = t / 8, j = t % 8;
            const float* We = (l == 0) ? We0 : (l == 1) ? We1 : We2;
            const float* ae = (l == 0) ? ae0 : (l == 1) ? ae1 : ae2;
            int C = (l == 2) ? 64 : 128;
            float s = 0.f;
            for (int c = 0; c < C; c++) s += We[j * C + c] * ae[c];
            g_v[l * 8 + j] = s;
        }
    }
    if (f < M * 32) {
        int r = f >> 5;
        int k0 = (f & 31) << 2;
        float4 v = *(const float4*)(X + (size_t)r * 128 + k0);
        int p = k0 >> 5, o = (k0 >> 4) & 1, kk = k0 & 15;
        int i = (kk >= 8) ? 1 : 0;
        int tq = (kk & 7) >> 1;
        int hb = p * 32 + tq * 8 + o * 4 + i * 2;
        __half2* hp = (__half2*)(g_xf + (size_t)r * 128);
        hp[hb >> 1]       = __floats2half2_rn(v.x, v.y);
        hp[(hb >> 1) + 4] = __floats2half2_rn(v.z, v.w);
        return;
    }
    int idx = f - M * 32;
    if (idx < 40960) {
        int l, e;
        if (idx < 16384)       { l = 0; e = idx; }
        else if (idx < 32768)  { l = 1; e = idx - 16384; }
        else                   { l = 2; e = idx - 32768; }
        int BN = (l == 2) ? 64 : 128;
        int k = e / BN, n = e % BN;
        const float* W = (l == 0) ? W0 : (l == 1) ? W1 : W2;
        __half* Wf = (l == 0) ? g_wf0 : (l == 1) ? g_wf1 : g_wf2;
        int p = k >> 5, o = (k >> 4) & 1, kk = k & 15;
        int i = (kk >= 8) ? 1 : 0;
        int tq = (kk & 7) >> 1, hs = k & 1;
        int lane = (n & 7) * 4 + tq;
        int word = ((n >> 3) * 4 + p) * 128 + lane * 4 + o * 2 + i;
        Wf[word * 2 + hs] = __float2half(W[k * BN + n]);
        return;
    }
    int i2 = idx - 40960;
    if (i2 < MAXN) g_deg[i2] = 0;
}

__global__ void count_kernel(const void* __restrict__ ei, int E, int n) {
    int e = blockIdx.x * blockDim.x + threadIdx.x;
    if (e >= E) return;
    int d = get_idx(ei, E + e);
    if ((unsigned)d < (unsigned)n) atomicAdd(&g_deg[d], 1);
}

__global__ void scan_kernel(int n) {
    __shared__ int wsum[32];
    int tid = threadIdx.x;
    int per = (n + 1023) / 1024;
    int st = tid * per;
    int en = min(st + per, n);
    int s = 0;
    for (int i = st; i < en; i++) s += g_deg[i];
    int lane = tid & 31, wid = tid >> 5;
    int v = s;
#pragma unroll
    for (int o = 1; o < 32; o <<= 1) {
        int t = __shfl_up_sync(0xffffffffu, v, o);
        if (lane >= o) v += t;
    }
    if (lane == 31) wsum[wid] = v;
    __syncthreads();
    if (wid == 0) {
        int w = wsum[lane];
#pragma unroll
        for (int o = 1; o < 32; o <<= 1) {
            int t = __shfl_up_sync(0xffffffffu, w, o);
            if (lane >= o) w += t;
        }
        wsum[lane] = w;
    }
    __syncthreads();
    int base = v - s + ((wid > 0) ? wsum[wid - 1] : 0);
    for (int i = st; i < en; i++) {
        g_off[i] = base;
        g_cur[i] = base;
        base += g_deg[i];
    }
    if (tid == 1023) g_off[n] = base;
}

// ---------------------------------------------------------------------------
__device__ __forceinline__ void edgefill_body(const float* __restrict__ ea,
                                              const void* __restrict__ ei,
                                              int e, int E, int n) {
    if (e >= E) return;
    int s = get_idx(ei, e);
    int d = get_idx(ei, E + e);
    if ((unsigned)d >= (unsigned)n || (unsigned)s >= (unsigned)n) return;
    float a[8];
#pragma unroll
    for (int j = 0; j < 8; j++) a[j] = ea[e * 8 + j];
    float c[3];
#pragma unroll
    for (int l = 0; l < 3; l++) {
        float sv = 0.f;
#pragma unroll
        for (int j = 0; j < 8; j++) sv += a[j] * g_v[l * 8 + j];
        c[l] = sv;
    }
    int p = atomicAdd(&g_cur[d], 1);
    if (p >= MAXE) return;
    g_csr[p] = make_int4(s, __float_as_int(c[0]), __float_as_int(c[1]),
                         __float_as_int(c[2]));
}

// ---------------------------------------------------------------------------
template <int BN>
__device__ __forceinline__ void gemm_body(const __half* __restrict__ Af,
                                          const __half* __restrict__ Wf,
                                          const float* __restrict__ as_,
                                          const float* __restrict__ ad_,
                                          __half* __restrict__ H, int M,
                                          int bid) {
    const int MI = (BN == 128) ? 2 : 1;
    const int RPW = (BN == 128) ? 32 : 16;
    __shared__ float Sp[512];
    int tid = threadIdx.x;
    int lane = tid & 31, wid = tid >> 5;
    int g = lane >> 2, tq = lane & 3;
    int wr = (BN == 128) ? (wid & 3) : wid;
    int wc = (BN == 128) ? (wid >> 2) : 0;
    int row0 = bid * 128;

    float4 acc[MI][8];
#pragma unroll
    for (int mi = 0; mi < MI; mi++)
#pragma unroll
        for (int nt = 0; nt < 8; nt++) acc[mi][nt] = make_float4(0.f, 0.f, 0.f, 0.f);

    const uint4* pa[MI][2];
#pragma unroll
    for (int mi = 0; mi < MI; mi++) {
        int rb = row0 + wr * RPW + mi * 16;
        pa[mi][0] = (const uint4*)Af + (size_t)(rb + g) * 16 + tq;
        pa[mi][1] = (const uint4*)Af + (size_t)(rb + g + 8) * 16 + tq;
    }
    const uint4* pb = (const uint4*)Wf + (size_t)(wc * 8 * 4) * 32 + lane;

#pragma unroll
    for (int p = 0; p < 4; p++) {
        uint4 qa[MI], qb[MI];
#pragma unroll
        for (int mi = 0; mi < MI; mi++) {
            qa[mi] = pa[mi][0][p * 4];
            qb[mi] = pa[mi][1][p * 4];
        }
#pragma unroll
        for (int nt = 0; nt < 8; nt++) {
            uint4 w = pb[(nt * 4 + p) * 32];
#pragma unroll
            for (int mi = 0; mi < MI; mi++) {
                mma_f16(acc[mi][nt], qa[mi].x, qb[mi].x, qa[mi].y, qb[mi].y,
                        w.x, w.y);
                mma_f16(acc[mi][nt], qa[mi].z, qb[mi].z, qa[mi].w, qb[mi].w,
                        w.z, w.w);
            }
        }
    }

    float s1l[MI], s2l[MI], s1h[MI], s2h[MI];
#pragma unroll
    for (int mi = 0; mi < MI; mi++) { s1l[mi]=s2l[mi]=s1h[mi]=s2h[mi]=0.f; }
#pragma unroll
    for (int mi = 0; mi < MI; mi++) {
        int rA = row0 + wr * RPW + mi * 16 + g;
#pragma unroll
        for (int nt = 0; nt < 8; nt++) {
            int c0 = wc * 64 + nt * 8 + 2 * tq;
            float w1 = as_[c0], w1b = as_[c0 + 1];
            float w2 = ad_[c0], w2b = ad_[c0 + 1];
            float4 c = acc[mi][nt];
            s1l[mi] += c.x * w1 + c.y * w1b;
            s2l[mi] += c.x * w2 + c.y * w2b;
            s1h[mi] += c.z * w1 + c.w * w1b;
            s2h[mi] += c.z * w2 + c.w * w2b;
            if (rA < M)
                *(__half2*)&H[(size_t)rA * BN + c0] = __floats2half2_rn(c.x, c.y);
            if (rA + 8 < M)
                *(__half2*)&H[(size_t)(rA + 8) * BN + c0] = __floats2half2_rn(c.z, c.w);
        }
    }
#pragma unroll
    for (int mi = 0; mi < MI; mi++) {
#pragma unroll
        for (int o = 1; o < 4; o <<= 1) {
            s1l[mi] += __shfl_xor_sync(0xffffffffu, s1l[mi], o);
            s2l[mi] += __shfl_xor_sync(0xffffffffu, s2l[mi], o);
            s1h[mi] += __shfl_xor_sync(0xffffffffu, s1h[mi], o);
            s2h[mi] += __shfl_xor_sync(0xffffffffu, s2h[mi], o);
        }
    }
    if (BN == 64) {
        if (tq == 0) {
            int rA = row0 + wr * RPW + g;
            if (rA < M)     { g_ss[rA] = s1l[0];     g_sd[rA] = s2l[0]; }
            if (rA + 8 < M) { g_ss[rA + 8] = s1h[0]; g_sd[rA + 8] = s2h[0]; }
        }
    } else {
        if (tq == 0) {
#pragma unroll
            for (int mi = 0; mi < MI; mi++) {
                int rib = wr * RPW + mi * 16 + g;
                Sp[wc * 128 + rib]           = s1l[mi];
                Sp[wc * 128 + rib + 8]       = s1h[mi];
                Sp[256 + wc * 128 + rib]     = s2l[mi];
                Sp[256 + wc * 128 + rib + 8] = s2h[mi];
            }
        }
        __syncthreads();
        if (tid < 128) {
            int r = row0 + tid;
            if (r < M) {
                g_ss[r] = Sp[tid] + Sp[128 + tid];
                g_sd[r] = Sp[256 + tid] + Sp[384 + tid];
            }
        }
    }
}

template <int BN>
__global__ void __launch_bounds__(256, 2)
gemm_frag(const __half* __restrict__ Af, const __half* __restrict__ Wf,
          const float* __restrict__ as_, const float* __restrict__ ad_,
          __half* __restrict__ H, int M) {
    gemm_body<BN>(Af, Wf, as_, ad_, H, M, blockIdx.x);
}

__global__ void __launch_bounds__(256, 2)
gemm0_edgefill(const __half* __restrict__ Af, const __half* __restrict__ Wf,
               const float* __restrict__ as_, const float* __restrict__ ad_,
               __half* __restrict__ H, int M, int gb,
               const float* __restrict__ ea, const void* __restrict__ ei,
               int E, int n) {
    if ((int)blockIdx.x < gb) {
        gemm_body<128>(Af, Wf, as_, ad_, H, M, blockIdx.x);
    } else {
        int e = (blockIdx.x - gb) * 256 + threadIdx.x;
        edgefill_body(ea, ei, e, E, n);
    }
}

// ---------------------------------------------------------------------------
// R14 split-warp aggregation: half-warp per edge, uint4 (16B) gathers.
// Lane owns cols l16*8..l16*8+7 in acc[8]; halves combined via shfl_xor(16).
__global__ void aggregate128(int layer, const float* __restrict__ bias,
                             __half* __restrict__ outf, int n) {
    int node = blockIdx.x * (blockDim.x >> 5) + (threadIdx.x >> 5);
    int lane = threadIdx.x & 31;
    if (node >= n) return;
    int e0 = g_off[node], e1 = g_off[node + 1];
    float sdn = g_sd[node];
    int half = lane >> 4, l16 = lane & 15;

    float denom = 0.f, csum = 0.f;
    float acc[8];
#pragma unroll
    for (int i = 0; i < 8; i++) acc[i] = 0.f;

    for (int jb = e0; jb < e1; jb += 32) {
        int j = jb + lane;
        float ex = 0.f;
        int s = 0;
        if (j < e1) {
            int4 pe = g_csr[j];
            s = pe.x;
            float cv = __int_as_float(layer == 0 ? pe.y : (layer == 1 ? pe.z : pe.w));
            csum += cv;
            float a = g_ss[s] + sdn + cv;
            a = (a > 0.f) ? a : 0.2f * a;
            ex = __expf(a);
            denom += ex;
        }
        int kmax = min(e1 - jb, 32);
        for (int k = 0; k < kmax; k += 8) {
            float ef[4]; int sv[4];
#pragma unroll
            for (int t = 0; t < 4; t++) {
                int idx = k + 2 * t + half;
                ef[t] = __shfl_sync(0xffffffffu, ex, idx);
                sv[t] = __shfl_sync(0xffffffffu, s, idx);
            }
            uint4 hv[4];
#pragma unroll
            for (int t = 0; t < 4; t++)
                hv[t] = ((const uint4*)(g_h + (size_t)sv[t] * 128))[l16];
#pragma unroll
            for (int t = 0; t < 4; t++) {
                float2 f0 = __half22float2(*(const __half2*)&hv[t].x);
                float2 f1 = __half22float2(*(const __half2*)&hv[t].y);
                float2 f2 = __half22float2(*(const __half2*)&hv[t].z);
                float2 f3 = __half22float2(*(const __half2*)&hv[t].w);
                acc[0] += ef[t] * f0.x; acc[1] += ef[t] * f0.y;
                acc[2] += ef[t] * f1.x; acc[3] += ef[t] * f1.y;
                acc[4] += ef[t] * f2.x; acc[5] += ef[t] * f2.y;
                acc[6] += ef[t] * f3.x; acc[7] += ef[t] * f3.y;
            }
        }
    }
    // full-warp reductions of scalar partials
#pragma unroll
    for (int o = 16; o; o >>= 1) {
        csum  += __shfl_xor_sync(0xffffffffu, csum, o);
        denom += __shfl_xor_sync(0xffffffffu, denom, o);
    }
    // combine the two half-warp accumulators (symmetric: both halves valid)
#pragma unroll
    for (int i = 0; i < 8; i++)
        acc[i] += __shfl_xor_sync(0xffffffffu, acc[i], 16);
    // folded self-loop
    float invd = 1.f / fmaxf((float)(e1 - e0), 1.f);
    float aself = g_ss[node] + sdn + csum * invd;
    aself = (aself > 0.f) ? aself : 0.2f * aself;
    float exs = __expf(aself);
    denom += exs;
    {
        uint4 hv = ((const uint4*)(g_h + (size_t)node * 128))[l16];
        float2 f0 = __half22float2(*(const __half2*)&hv.x);
        float2 f1 = __half22float2(*(const __half2*)&hv.y);
        float2 f2 = __half22float2(*(const __half2*)&hv.z);
        float2 f3 = __half22float2(*(const __half2*)&hv.w);
        acc[0] += exs * f0.x; acc[1] += exs * f0.y;
        acc[2] += exs * f1.x; acc[3] += exs * f1.y;
        acc[4] += exs * f2.x; acc[5] += exs * f2.y;
        acc[6] += exs * f3.x; acc[7] += exs * f3.y;
    }
    if (half == 0) {
        float inv = 1.f / (denom + 1e-16f);
        int c0 = l16 * 8;
        float4 b0 = *(const float4*)(bias + c0);
        float4 b1 = *(const float4*)(bias + c0 + 4);
        float r[8];
        r[0] = fmaxf(acc[0] * inv + b0.x, 0.f);
        r[1] = fmaxf(acc[1] * inv + b0.y, 0.f);
        r[2] = fmaxf(acc[2] * inv + b0.z, 0.f);
        r[3] = fmaxf(acc[3] * inv + b0.w, 0.f);
        r[4] = fmaxf(acc[4] * inv + b1.x, 0.f);
        r[5] = fmaxf(acc[5] * inv + b1.y, 0.f);
        r[6] = fmaxf(acc[6] * inv + b1.z, 0.f);
        r[7] = fmaxf(acc[7] * inv + b1.w, 0.f);
        // fp16 frag store for cols c0..c0+7:
        // half2 index = p*16 + tq*4 + o*2 + i, tq=0..3 for col pairs
        int p = l16 >> 2, o = (l16 >> 1) & 1, i = l16 & 1;
        __half2* op = (__half2*)(outf + (size_t)node * 128);
        int base = p * 16 + o * 2 + i;
        op[base]      = __floats2half2_rn(r[0], r[1]);
        op[base + 4]  = __floats2half2_rn(r[2], r[3]);
        op[base + 8]  = __floats2half2_rn(r[4], r[5]);
        op[base + 12] = __floats2half2_rn(r[6], r[7]);
    }
}

// C=64 version: half-warp per edge, uint2 (8B) gathers; lane owns cols l16*4..+3.
__global__ void aggregate64(int layer, const float* __restrict__ bias,
                            float* __restrict__ out, int n) {
    int node = blockIdx.x * (blockDim.x >> 5) + (threadIdx.x >> 5);
    int lane = threadIdx.x & 31;
    if (node >= n) return;
    int e0 = g_off[node], e1 = g_off[node + 1];
    float sdn = g_sd[node];
    int half = lane >> 4, l16 = lane & 15;

    float denom = 0.f, csum = 0.f;
    float acc[4];
#pragma unroll
    for (int i = 0; i < 4; i++) acc[i] = 0.f;

    for (int jb = e0; jb < e1; jb += 32) {
        int j = jb + lane;
        float ex = 0.f;
        int s = 0;
        if (j < e1) {
            int4 pe = g_csr[j];
            s = pe.x;
            float cv = __int_as_float(layer == 0 ? pe.y : (layer == 1 ? pe.z : pe.w));
            csum += cv;
            float a = g_ss[s] + sdn + cv;
            a = (a > 0.f) ? a : 0.2f * a;
            ex = __expf(a);
            denom += ex;
        }
        int kmax = min(e1 - jb, 32);
        for (int k = 0; k < kmax; k += 8) {
            float ef[4]; int sv[4];
#pragma unroll
            for (int t = 0; t < 4; t++) {
                int idx = k + 2 * t + half;
                ef[t] = __shfl_sync(0xffffffffu, ex, idx);
                sv[t] = __shfl_sync(0xffffffffu, s, idx);
            }
            uint2 hv[4];
#pragma unroll
            for (int t = 0; t < 4; t++)
                hv[t] = ((const uint2*)(g_h + (size_t)sv[t] * 64))[l16];
#pragma unroll
            for (int t = 0; t < 4; t++) {
                float2 f0 = __half22float2(*(const __half2*)&hv[t].x);
                float2 f1 = __half22float2(*(const __half2*)&hv[t].y);
                acc[0] += ef[t] * f0.x; acc[1] += ef[t] * f0.y;
                acc[2] += ef[t] * f1.x; acc[3] += ef[t] * f1.y;
            }
        }
    }
#pragma unroll
    for (int o = 16; o; o >>= 1) {
        csum  += __shfl_xor_sync(0xffffffffu, csum, o);
        denom += __shfl_xor_sync(0xffffffffu, denom, o);
    }
#pragma unroll
    for (int i = 0; i < 4; i++)
        acc[i] += __shfl_xor_sync(0xffffffffu, acc[i], 16);
    float invd = 1.f / fmaxf((float)(e1 - e0), 1.f);
    float aself = g_ss[node] + sdn + csum * invd;
    aself = (aself > 0.f) ? aself : 0.2f * aself;
    float exs = __expf(aself);
    denom += exs;
    {
        uint2 hv = ((const uint2*)(g_h + (size_t)node * 64))[l16];
        float2 f0 = __half22float2(*(const __half2*)&hv.x);
        float2 f1 = __half22float2(*(const __half2*)&hv.y);
        acc[0] += exs * f0.x; acc[1] += exs * f0.y;
        acc[2] += exs * f1.x; acc[3] += exs * f1.y;
    }
    if (half == 0) {
        float inv = 1.f / (denom + 1e-16f);
        float4 b = *(const float4*)(bias + l16 * 4);
        float4 r;
        r.x = acc[0] * inv + b.x;
        r.y = acc[1] * inv + b.y;
        r.z = acc[2] * inv + b.z;
        r.w = acc[3] * inv + b.w;
        *(float4*)(out + (size_t)node * 64 + l16 * 4) = r;
    }
}

extern "C" void kernel_launch(void* const* d_in, const int* in_sizes, int n_in,
                              void* d_out, int out_size) {
    const float* x      = (const float*)d_in[0];
    const void*  ei     = d_in[1];
    const float* ea     = (const float*)d_in[2];
    const float* W[3]  = {(const float*)d_in[3],  (const float*)d_in[9],  (const float*)d_in[15]};
    const float* As_[3]= {(const float*)d_in[4],  (const float*)d_in[10], (const float*)d_in[16]};
    const float* Ad[3] = {(const float*)d_in[5],  (const float*)d_in[11], (const float*)d_in[17]};
    const float* We[3] = {(const float*)d_in[6],  (const float*)d_in[12], (const float*)d_in[18]};
    const float* Ae[3] = {(const float*)d_in[7],  (const float*)d_in[13], (const float*)d_in[19]};
    const float* Bb[3] = {(const float*)d_in[8],  (const float*)d_in[14], (const float*)d_in[20]};

    int N = in_sizes[0] / 128;
    int E = in_sizes[2] / 8;
    int forced = (in_sizes[1] == 4 * E) ? 1 : -1;

    static __half* h = nullptr;
    static __half *xf = nullptr, *bufAf = nullptr, *bufBf = nullptr;
    static __half *wf0 = nullptr, *wf1 = nullptr, *wf2 = nullptr;
    if (!h) {
        cudaGetSymbolAddress((void**)&h,     g_h);
        cudaGetSymbolAddress((void**)&xf,    g_xf);
        cudaGetSymbolAddress((void**)&bufAf, g_bufAf);
        cudaGetSymbolAddress((void**)&bufBf, g_bufBf);
        cudaGetSymbolAddress((void**)&wf0,   g_wf0);
        cudaGetSymbolAddress((void**)&wf1,   g_wf1);
        cudaGetSymbolAddress((void**)&wf2,   g_wf2);
    }

    int gb = (N + 127) / 128;
    int nb = (N + 7) / 8;
    int eb = (E + 255) / 256;

    xform_init_kernel<<<(N * 32 + 40960 + MAXN + 255) / 256, 256>>>(
        x, W[0], W[1], W[2], (const int*)ei, forced,
        We[0], Ae[0], We[1], Ae[1], We[2], Ae[2], N);
    count_kernel<<<eb, 256>>>(ei, E, N);
    scan_kernel<<<1, 1024>>>(N);
    gemm0_edgefill<<<gb + eb, 256>>>(xf, wf0, As_[0], Ad[0], h, N, gb,
                                     ea, ei, E, N);
    aggregate128<<<nb, 256>>>(0, Bb[0], bufAf, N);
    gemm_frag<128><<<gb, 256>>>(bufAf, wf1, As_[1], Ad[1], h, N);
    aggregate128<<<nb, 256>>>(1, Bb[1], bufBf, N);
    gemm_frag<64><<<gb, 256>>>(bufBf, wf2, As_[2], Ad[2], h, N);
    aggregate64<<<nb, 256>>>(2, Bb[2], (float*)d_out, N);
}

// round 15
// speedup vs baseline: 1.7419x; 1.3721x over previous
#include <cuda_runtime.h>
#include <cuda_fp16.h>
#include <math.h>

// ---------------------------------------------------------------------------
// GAT 3-layer pipeline. R15 = R14 with the scan rewritten: coalesced int4
// block scan (13 rounds) instead of per-thread contiguous chunks whose
// stride-196B access pattern serialized ~150k L1 wavefronts on one SM.
// ---------------------------------------------------------------------------

#define MAXN 50048
#define MAXE 600064

__device__ __half   g_h[MAXN * 128];
__device__ __half   g_xf[MAXN * 128];
__device__ __half   g_bufAf[MAXN * 128];
__device__ __half   g_bufBf[MAXN * 128];
__device__ __half   g_wf0[16384];
__device__ __half   g_wf1[16384];
__device__ __half   g_wf2[8192];
__device__ float    g_ss[MAXN];
__device__ float    g_sd[MAXN];
__device__ int4     g_csr[MAXE];
__device__ int      g_deg[MAXN];
__device__ int      g_off[MAXN + 1];
__device__ int      g_cur[MAXN];
__device__ float    g_v[24];
__device__ int      g_is64;

__device__ __forceinline__ int get_idx(const void* ei, int i) {
    if (g_is64) return (int)((const long long*)ei)[i];
    return ((const int*)ei)[i];
}

__device__ __forceinline__ void mma_f16(float4& c, unsigned a0, unsigned a1,
                                        unsigned a2, unsigned a3,
                                        unsigned b0, unsigned b1) {
    asm volatile(
        "mma.sync.aligned.m16n8k16.row.col.f32.f16.f16.f32 "
        "{%0,%1,%2,%3}, {%4,%5,%6,%7}, {%8,%9}, {%0,%1,%2,%3};"
        : "+f"(c.x), "+f"(c.y), "+f"(c.z), "+f"(c.w)
        : "r"(a0), "r"(a1), "r"(a2), "r"(a3), "r"(b0), "r"(b1));
}

// ---------------------------------------------------------------------------
__global__ void xform_init_kernel(const float* __restrict__ X,
                                  const float* __restrict__ W0,
                                  const float* __restrict__ W1,
                                  const float* __restrict__ W2,
                                  const int* __restrict__ eiw, int forced,
                                  const float* We0, const float* ae0,
                                  const float* We1, const float* ae1,
                                  const float* We2, const float* ae2,
                                  int M) {
    int f = blockIdx.x * blockDim.x + threadIdx.x;
    if (blockIdx.x == 0) {
        if (threadIdx.x == 0) {
            if (forced >= 0) g_is64 = forced;
            else {
                int is64 = 1;
                for (int j = 1; j < 32; j += 2)
                    if (eiw[j] != 0) is64 = 0;
                g_is64 = is64;
            }
        }
        int t = (int)threadIdx.x - 32;
        if (t >= 0 && t < 24) {
            int l = t / 8, j = t % 8;
            const float* We = (l == 0) ? We0 : (l == 1) ? We1 : We2;
            const float* ae = (l == 0) ? ae0 : (l == 1) ? ae1 : ae2;
            int C = (l == 2) ? 64 : 128;
            float s = 0.f;
            for (int c = 0; c < C; c++) s += We[j * C + c] * ae[c];
            g_v[l * 8 + j] = s;
        }
    }
    if (f < M * 32) {
        int r = f >> 5;
        int k0 = (f & 31) << 2;
        float4 v = *(const float4*)(X + (size_t)r * 128 + k0);
        int p = k0 >> 5, o = (k0 >> 4) & 1, kk = k0 & 15;
        int i = (kk >= 8) ? 1 : 0;
        int tq = (kk & 7) >> 1;
        int hb = p * 32 + tq * 8 + o * 4 + i * 2;
        __half2* hp = (__half2*)(g_xf + (size_t)r * 128);
        hp[hb >> 1]       = __floats2half2_rn(v.x, v.y);
        hp[(hb >> 1) + 4] = __floats2half2_rn(v.z, v.w);
        return;
    }
    int idx = f - M * 32;
    if (idx < 40960) {
        int l, e;
        if (idx < 16384)       { l = 0; e = idx; }
        else if (idx < 32768)  { l = 1; e = idx - 16384; }
        else                   { l = 2; e = idx - 32768; }
        int BN = (l == 2) ? 64 : 128;
        int k = e / BN, n = e % BN;
        const float* W = (l == 0) ? W0 : (l == 1) ? W1 : W2;
        __half* Wf = (l == 0) ? g_wf0 : (l == 1) ? g_wf1 : g_wf2;
        int p = k >> 5, o = (k >> 4) & 1, kk = k & 15;
        int i = (kk >= 8) ? 1 : 0;
        int tq = (kk & 7) >> 1, hs = k & 1;
        int lane = (n & 7) * 4 + tq;
        int word = ((n >> 3) * 4 + p) * 128 + lane * 4 + o * 2 + i;
        Wf[word * 2 + hs] = __float2half(W[k * BN + n]);
        return;
    }
    int i2 = idx - 40960;
    if (i2 < MAXN) g_deg[i2] = 0;
}

__global__ void count_kernel(const void* __restrict__ ei, int E, int n) {
    int e = blockIdx.x * blockDim.x + threadIdx.x;
    if (e >= E) return;
    int d = get_idx(ei, E + e);
    if ((unsigned)d < (unsigned)n) atomicAdd(&g_deg[d], 1);
}

// R15: coalesced int4 block scan. Each round covers 4096 elements; thread t
// owns [base+4t, base+4t+4). deg[n..MAXN) is zero, so every g_off[i] is the
// exact prefix sum -- including g_off[n].
__global__ void scan_kernel(int n) {
    __shared__ int wsum[32];
    __shared__ int carry;
    int tid = threadIdx.x, lane = tid & 31, wid = tid >> 5;
    if (tid == 0) carry = 0;
    __syncthreads();
    for (int base = 0; base < MAXN; base += 4096) {
        int i0 = base + tid * 4;
        int4 v = make_int4(0, 0, 0, 0);
        bool ok = (i0 + 3 < MAXN);
        if (ok) v = *(const int4*)&g_deg[i0];
        int s = v.x + v.y + v.z + v.w;
        int incl = s;
#pragma unroll
        for (int o = 1; o < 32; o <<= 1) {
            int t = __shfl_up_sync(0xffffffffu, incl, o);
            if (lane >= o) incl += t;
        }
        if (lane == 31) wsum[wid] = incl;
        __syncthreads();
        if (wid == 0) {
            int w = wsum[lane];
#pragma unroll
            for (int o = 1; o < 32; o <<= 1) {
                int t = __shfl_up_sync(0xffffffffu, w, o);
                if (lane >= o) w += t;
            }
            wsum[lane] = w;
        }
        __syncthreads();
        int excl = carry + incl - s + ((wid > 0) ? wsum[wid - 1] : 0);
        if (ok) {
            int4 o4;
            o4.x = excl;
            o4.y = o4.x + v.x;
            o4.z = o4.y + v.y;
            o4.w = o4.z + v.z;
            *(int4*)&g_off[i0] = o4;
            *(int4*)&g_cur[i0] = o4;
        }
        int total = wsum[31];
        __syncthreads();
        if (tid == 0) carry += total;
        __syncthreads();
    }
}

// ---------------------------------------------------------------------------
__device__ __forceinline__ void edgefill_body(const float* __restrict__ ea,
                                              const void* __restrict__ ei,
                                              int e, int E, int n) {
    if (e >= E) return;
    int s = get_idx(ei, e);
    int d = get_idx(ei, E + e);
    if ((unsigned)d >= (unsigned)n || (unsigned)s >= (unsigned)n) return;
    float a[8];
#pragma unroll
    for (int j = 0; j < 8; j++) a[j] = ea[e * 8 + j];
    float c[3];
#pragma unroll
    for (int l = 0; l < 3; l++) {
        float sv = 0.f;
#pragma unroll
        for (int j = 0; j < 8; j++) sv += a[j] * g_v[l * 8 + j];
        c[l] = sv;
    }
    int p = atomicAdd(&g_cur[d], 1);
    if (p >= MAXE) return;
    g_csr[p] = make_int4(s, __float_as_int(c[0]), __float_as_int(c[1]),
                         __float_as_int(c[2]));
}

// ---------------------------------------------------------------------------
template <int BN>
__device__ __forceinline__ void gemm_body(const __half* __restrict__ Af,
                                          const __half* __restrict__ Wf,
                                          const float* __restrict__ as_,
                                          const float* __restrict__ ad_,
                                          __half* __restrict__ H, int M,
                                          int bid) {
    const int MI = (BN == 128) ? 2 : 1;
    const int RPW = (BN == 128) ? 32 : 16;
    __shared__ float Sp[512];
    int tid = threadIdx.x;
    int lane = tid & 31, wid = tid >> 5;
    int g = lane >> 2, tq = lane & 3;
    int wr = (BN == 128) ? (wid & 3) : wid;
    int wc = (BN == 128) ? (wid >> 2) : 0;
    int row0 = bid * 128;

    float4 acc[MI][8];
#pragma unroll
    for (int mi = 0; mi < MI; mi++)
#pragma unroll
        for (int nt = 0; nt < 8; nt++) acc[mi][nt] = make_float4(0.f, 0.f, 0.f, 0.f);

    const uint4* pa[MI][2];
#pragma unroll
    for (int mi = 0; mi < MI; mi++) {
        int rb = row0 + wr * RPW + mi * 16;
        pa[mi][0] = (const uint4*)Af + (size_t)(rb + g) * 16 + tq;
        pa[mi][1] = (const uint4*)Af + (size_t)(rb + g + 8) * 16 + tq;
    }
    const uint4* pb = (const uint4*)Wf + (size_t)(wc * 8 * 4) * 32 + lane;

#pragma unroll
    for (int p = 0; p < 4; p++) {
        uint4 qa[MI], qb[MI];
#pragma unroll
        for (int mi = 0; mi < MI; mi++) {
            qa[mi] = pa[mi][0][p * 4];
            qb[mi] = pa[mi][1][p * 4];
        }
#pragma unroll
        for (int nt = 0; nt < 8; nt++) {
            uint4 w = pb[(nt * 4 + p) * 32];
#pragma unroll
            for (int mi = 0; mi < MI; mi++) {
                mma_f16(acc[mi][nt], qa[mi].x, qb[mi].x, qa[mi].y, qb[mi].y,
                        w.x, w.y);
                mma_f16(acc[mi][nt], qa[mi].z, qb[mi].z, qa[mi].w, qb[mi].w,
                        w.z, w.w);
            }
        }
    }

    float s1l[MI], s2l[MI], s1h[MI], s2h[MI];
#pragma unroll
    for (int mi = 0; mi < MI; mi++) { s1l[mi]=s2l[mi]=s1h[mi]=s2h[mi]=0.f; }
#pragma unroll
    for (int mi = 0; mi < MI; mi++) {
        int rA = row0 + wr * RPW + mi * 16 + g;
#pragma unroll
        for (int nt = 0; nt < 8; nt++) {
            int c0 = wc * 64 + nt * 8 + 2 * tq;
            float w1 = as_[c0], w1b = as_[c0 + 1];
            float w2 = ad_[c0], w2b = ad_[c0 + 1];
            float4 c = acc[mi][nt];
            s1l[mi] += c.x * w1 + c.y * w1b;
            s2l[mi] += c.x * w2 + c.y * w2b;
            s1h[mi] += c.z * w1 + c.w * w1b;
            s2h[mi] += c.z * w2 + c.w * w2b;
            if (rA < M)
                *(__half2*)&H[(size_t)rA * BN + c0] = __floats2half2_rn(c.x, c.y);
            if (rA + 8 < M)
                *(__half2*)&H[(size_t)(rA + 8) * BN + c0] = __floats2half2_rn(c.z, c.w);
        }
    }
#pragma unroll
    for (int mi = 0; mi < MI; mi++) {
#pragma unroll
        for (int o = 1; o < 4; o <<= 1) {
            s1l[mi] += __shfl_xor_sync(0xffffffffu, s1l[mi], o);
            s2l[mi] += __shfl_xor_sync(0xffffffffu, s2l[mi], o);
            s1h[mi] += __shfl_xor_sync(0xffffffffu, s1h[mi], o);
            s2h[mi] += __shfl_xor_sync(0xffffffffu, s2h[mi], o);
        }
    }
    if (BN == 64) {
        if (tq == 0) {
            int rA = row0 + wr * RPW + g;
            if (rA < M)     { g_ss[rA] = s1l[0];     g_sd[rA] = s2l[0]; }
            if (rA + 8 < M) { g_ss[rA + 8] = s1h[0]; g_sd[rA + 8] = s2h[0]; }
        }
    } else {
        if (tq == 0) {
#pragma unroll
            for (int mi = 0; mi < MI; mi++) {
                int rib = wr * RPW + mi * 16 + g;
                Sp[wc * 128 + rib]           = s1l[mi];
                Sp[wc * 128 + rib + 8]       = s1h[mi];
                Sp[256 + wc * 128 + rib]     = s2l[mi];
                Sp[256 + wc * 128 + rib + 8] = s2h[mi];
            }
        }
        __syncthreads();
        if (tid < 128) {
            int r = row0 + tid;
            if (r < M) {
                g_ss[r] = Sp[tid] + Sp[128 + tid];
                g_sd[r] = Sp[256 + tid] + Sp[384 + tid];
            }
        }
    }
}

template <int BN>
__global__ void __launch_bounds__(256, 2)
gemm_frag(const __half* __restrict__ Af, const __half* __restrict__ Wf,
          const float* __restrict__ as_, const float* __restrict__ ad_,
          __half* __restrict__ H, int M) {
    gemm_body<BN>(Af, Wf, as_, ad_, H, M, blockIdx.x);
}

__global__ void __launch_bounds__(256, 2)
gemm0_edgefill(const __half* __restrict__ Af, const __half* __restrict__ Wf,
               const float* __restrict__ as_, const float* __restrict__ ad_,
               __half* __restrict__ H, int M, int gb,
               const float* __restrict__ ea, const void* __restrict__ ei,
               int E, int n) {
    if ((int)blockIdx.x < gb) {
        gemm_body<128>(Af, Wf, as_, ad_, H, M, blockIdx.x);
    } else {
        int e = (blockIdx.x - gb) * 256 + threadIdx.x;
        edgefill_body(ea, ei, e, E, n);
    }
}

// ---------------------------------------------------------------------------
// Split-warp aggregation (R14): half-warp per edge, uint4 gathers.
__global__ void aggregate128(int layer, const float* __restrict__ bias,
                             __half* __restrict__ outf, int n) {
    int node = blockIdx.x * (blockDim.x >> 5) + (threadIdx.x >> 5);
    int lane = threadIdx.x & 31;
    if (node >= n) return;
    int e0 = g_off[node], e1 = g_off[node + 1];
    float sdn = g_sd[node];
    int half = lane >> 4, l16 = lane & 15;

    float denom = 0.f, csum = 0.f;
    float acc[8];
#pragma unroll
    for (int i = 0; i < 8; i++) acc[i] = 0.f;

    for (int jb = e0; jb < e1; jb += 32) {
        int j = jb + lane;
        float ex = 0.f;
        int s = 0;
        if (j < e1) {
            int4 pe = g_csr[j];
            s = pe.x;
            float cv = __int_as_float(layer == 0 ? pe.y : (layer == 1 ? pe.z : pe.w));
            csum += cv;
            float a = g_ss[s] + sdn + cv;
            a = (a > 0.f) ? a : 0.2f * a;
            ex = __expf(a);
            denom += ex;
        }
        int kmax = min(e1 - jb, 32);
        for (int k = 0; k < kmax; k += 8) {
            float ef[4]; int sv[4];
#pragma unroll
            for (int t = 0; t < 4; t++) {
                int idx = k + 2 * t + half;
                ef[t] = __shfl_sync(0xffffffffu, ex, idx);
                sv[t] = __shfl_sync(0xffffffffu, s, idx);
            }
            uint4 hv[4];
#pragma unroll
            for (int t = 0; t < 4; t++)
                hv[t] = ((const uint4*)(g_h + (size_t)sv[t] * 128))[l16];
#pragma unroll
            for (int t = 0; t < 4; t++) {
                float2 f0 = __half22float2(*(const __half2*)&hv[t].x);
                float2 f1 = __half22float2(*(const __half2*)&hv[t].y);
                float2 f2 = __half22float2(*(const __half2*)&hv[t].z);
                float2 f3 = __half22float2(*(const __half2*)&hv[t].w);
                acc[0] += ef[t] * f0.x; acc[1] += ef[t] * f0.y;
                acc[2] += ef[t] * f1.x; acc[3] += ef[t] * f1.y;
                acc[4] += ef[t] * f2.x; acc[5] += ef[t] * f2.y;
                acc[6] += ef[t] * f3.x; acc[7] += ef[t] * f3.y;
            }
        }
    }
#pragma unroll
    for (int o = 16; o; o >>= 1) {
        csum  += __shfl_xor_sync(0xffffffffu, csum, o);
        denom += __shfl_xor_sync(0xffffffffu, denom, o);
    }
#pragma unroll
    for (int i = 0; i < 8; i++)
        acc[i] += __shfl_xor_sync(0xffffffffu, acc[i], 16);
    float invd = 1.f / fmaxf((float)(e1 - e0), 1.f);
    float aself = g_ss[node] + sdn + csum * invd;
    aself = (aself > 0.f) ? aself : 0.2f * aself;
    float exs = __expf(aself);
    denom += exs;
    {
        uint4 hv = ((const uint4*)(g_h + (size_t)node * 128))[l16];
        float2 f0 = __half22float2(*(const __half2*)&hv.x);
        float2 f1 = __half22float2(*(const __half2*)&hv.y);
        float2 f2 = __half22float2(*(const __half2*)&hv.z);
        float2 f3 = __half22float2(*(const __half2*)&hv.w);
        acc[0] += exs * f0.x; acc[1] += exs * f0.y;
        acc[2] += exs * f1.x; acc[3] += exs * f1.y;
        acc[4] += exs * f2.x; acc[5] += exs * f2.y;
        acc[6] += exs * f3.x; acc[7] += exs * f3.y;
    }
    if (half == 0) {
        float inv = 1.f / (denom + 1e-16f);
        int c0 = l16 * 8;
        float4 b0 = *(const float4*)(bias + c0);
        float4 b1 = *(const float4*)(bias + c0 + 4);
        float r[8];
        r[0] = fmaxf(acc[0] * inv + b0.x, 0.f);
        r[1] = fmaxf(acc[1] * inv + b0.y, 0.f);
        r[2] = fmaxf(acc[2] * inv + b0.z, 0.f);
        r[3] = fmaxf(acc[3] * inv + b0.w, 0.f);
        r[4] = fmaxf(acc[4] * inv + b1.x, 0.f);
        r[5] = fmaxf(acc[5] * inv + b1.y, 0.f);
        r[6] = fmaxf(acc[6] * inv + b1.z, 0.f);
        r[7] = fmaxf(acc[7] * inv + b1.w, 0.f);
        int p = l16 >> 2, o = (l16 >> 1) & 1, i = l16 & 1;
        __half2* op = (__half2*)(outf + (size_t)node * 128);
        int base = p * 16 + o * 2 + i;
        op[base]      = __floats2half2_rn(r[0], r[1]);
        op[base + 4]  = __floats2half2_rn(r[2], r[3]);
        op[base + 8]  = __floats2half2_rn(r[4], r[5]);
        op[base + 12] = __floats2half2_rn(r[6], r[7]);
    }
}

__global__ void aggregate64(int layer, const float* __restrict__ bias,
                            float* __restrict__ out, int n) {
    int node = blockIdx.x * (blockDim.x >> 5) + (threadIdx.x >> 5);
    int lane = threadIdx.x & 31;
    if (node >= n) return;
    int e0 = g_off[node], e1 = g_off[node + 1];
    float sdn = g_sd[node];
    int half = lane >> 4, l16 = lane & 15;

    float denom = 0.f, csum = 0.f;
    float acc[4];
#pragma unroll
    for (int i = 0; i < 4; i++) acc[i] = 0.f;

    for (int jb = e0; jb < e1; jb += 32) {
        int j = jb + lane;
        float ex = 0.f;
        int s = 0;
        if (j < e1) {
            int4 pe = g_csr[j];
            s = pe.x;
            float cv = __int_as_float(layer == 0 ? pe.y : (layer == 1 ? pe.z : pe.w));
            csum += cv;
            float a = g_ss[s] + sdn + cv;
            a = (a > 0.f) ? a : 0.2f * a;
            ex = __expf(a);
            denom += ex;
        }
        int kmax = min(e1 - jb, 32);
        for (int k = 0; k < kmax; k += 8) {
            float ef[4]; int sv[4];
#pragma unroll
            for (int t = 0; t < 4; t++) {
                int idx = k + 2 * t + half;
                ef[t] = __shfl_sync(0xffffffffu, ex, idx);
                sv[t] = __shfl_sync(0xffffffffu, s, idx);
            }
            uint2 hv[4];
#pragma unroll
            for (int t = 0; t < 4; t++)
                hv[t] = ((const uint2*)(g_h + (size_t)sv[t] * 64))[l16];
#pragma unroll
            for (int t = 0; t < 4; t++) {
                float2 f0 = __half22float2(*(const __half2*)&hv[t].x);
                float2 f1 = __half22float2(*(const __half2*)&hv[t].y);
                acc[0] += ef[t] * f0.x; acc[1] += ef[t] * f0.y;
                acc[2] += ef[t] * f1.x; acc[3] += ef[t] * f1.y;
            }
        }
    }
#pragma unroll
    for (int o = 16; o; o >>= 1) {
        csum  += __shfl_xor_sync(0xffffffffu, csum, o);
        denom += __shfl_xor_sync(0xffffffffu, denom, o);
    }
#pragma unroll
    for (int i = 0; i < 4; i++)
        acc[i] += __shfl_xor_sync(0xffffffffu, acc[i], 16);
    float invd = 1.f / fmaxf((float)(e1 - e0), 1.f);
    float aself = g_ss[node] + sdn + csum * invd;
    aself = (aself > 0.f) ? aself : 0.2f * aself;
    float exs = __expf(aself);
    denom += exs;
    {
        uint2 hv = ((const uint2*)(g_h + (size_t)node * 64))[l16];
        float2 f0 = __half22float2(*(const __half2*)&hv.x);
        float2 f1 = __half22float2(*(const __half2*)&hv.y);
        acc[0] += exs * f0.x; acc[1] += exs * f0.y;
        acc[2] += exs * f1.x; acc[3] += exs * f1.y;
    }
    if (half == 0) {
        float inv = 1.f / (denom + 1e-16f);
        float4 b = *(const float4*)(bias + l16 * 4);
        float4 r;
        r.x = acc[0] * inv + b.x;
        r.y = acc[1] * inv + b.y;
        r.z = acc[2] * inv + b.z;
        r.w = acc[3] * inv + b.w;
        *(float4*)(out + (size_t)node * 64 + l16 * 4) = r;
    }
}

extern "C" void kernel_launch(void* const* d_in, const int* in_sizes, int n_in,
                              void* d_out, int out_size) {
    const float* x      = (const float*)d_in[0];
    const void*  ei     = d_in[1];
    const float* ea     = (const float*)d_in[2];
    const float* W[3]  = {(const float*)d_in[3],  (const float*)d_in[9],  (const float*)d_in[15]};
    const float* As_[3]= {(const float*)d_in[4],  (const float*)d_in[10], (const float*)d_in[16]};
    const float* Ad[3] = {(const float*)d_in[5],  (const float*)d_in[11], (const float*)d_in[17]};
    const float* We[3] = {(const float*)d_in[6],  (const float*)d_in[12], (const float*)d_in[18]};
    const float* Ae[3] = {(const float*)d_in[7],  (const float*)d_in[13], (const float*)d_in[19]};
    const float* Bb[3] = {(const float*)d_in[8],  (const float*)d_in[14], (const float*)d_in[20]};

    int N = in_sizes[0] / 128;
    int E = in_sizes[2] / 8;
    int forced = (in_sizes[1] == 4 * E) ? 1 : -1;

    static __half* h = nullptr;
    static __half *xf = nullptr, *bufAf = nullptr, *bufBf = nullptr;
    static __half *wf0 = nullptr, *wf1 = nullptr, *wf2 = nullptr;
    if (!h) {
        cudaGetSymbolAddress((void**)&h,     g_h);
        cudaGetSymbolAddress((void**)&xf,    g_xf);
        cudaGetSymbolAddress((void**)&bufAf, g_bufAf);
        cudaGetSymbolAddress((void**)&bufBf, g_bufBf);
        cudaGetSymbolAddress((void**)&wf0,   g_wf0);
        cudaGetSymbolAddress((void**)&wf1,   g_wf1);
        cudaGetSymbolAddress((void**)&wf2,   g_wf2);
    }

    int gb = (N + 127) / 128;
    int nb = (N + 7) / 8;
    int eb = (E + 255) / 256;

    xform_init_kernel<<<(N * 32 + 40960 + MAXN + 255) / 256, 256>>>(
        x, W[0], W[1], W[2], (const int*)ei, forced,
        We[0], Ae[0], We[1], Ae[1], We[2], Ae[2], N);
    count_kernel<<<eb, 256>>>(ei, E, N);
    scan_kernel<<<1, 1024>>>(N);
    gemm0_edgefill<<<gb + eb, 256>>>(xf, wf0, As_[0], Ad[0], h, N, gb,
                                     ea, ei, E, N);
    aggregate128<<<nb, 256>>>(0, Bb[0], bufAf, N);
    gemm_frag<128><<<gb, 256>>>(bufAf, wf1, As_[1], Ad[1], h, N);
    aggregate128<<<nb, 256>>>(1, Bb[1], bufBf, N);
    gemm_frag<64><<<gb, 256>>>(bufBf, wf2, As_[2], Ad[2], h, N);
    aggregate64<<<nb, 256>>>(2, Bb[2], (float*)d_out, N);
}

// round 17
// speedup vs baseline: 1.8324x; 1.0519x over previous
#include <cuda_runtime.h>
#include <cuda_fp16.h>
#include <math.h>

// ---------------------------------------------------------------------------
// GAT 3-layer pipeline. R17 = R16 with the shuffle-mask fix: half-warp-per-
// node aggregation must use the 16-lane SEGMENT mask (0xFFFF << (lane&16))
// in every __shfl_sync, because the two segments of a warp diverge (different
// nodes / degrees) and a full-warp mask is UB under that divergence.
// ---------------------------------------------------------------------------

#define MAXN 50048
#define MAXE 600064

__device__ __half   g_h[MAXN * 128];
__device__ __half   g_xf[MAXN * 128];
__device__ __half   g_bufAf[MAXN * 128];
__device__ __half   g_bufBf[MAXN * 128];
__device__ __half   g_wf0[16384];
__device__ __half   g_wf1[16384];
__device__ __half   g_wf2[8192];
__device__ float    g_ss[MAXN];
__device__ float    g_sd[MAXN];
__device__ int4     g_csr[MAXE];
__device__ int      g_deg[MAXN];
__device__ int      g_off[MAXN + 1];
__device__ int      g_cur[MAXN];
__device__ float    g_v[24];
__device__ int      g_is64;

__device__ __forceinline__ int get_idx(const void* ei, int i) {
    if (g_is64) return (int)((const long long*)ei)[i];
    return ((const int*)ei)[i];
}

__device__ __forceinline__ void mma_f16(float4& c, unsigned a0, unsigned a1,
                                        unsigned a2, unsigned a3,
                                        unsigned b0, unsigned b1) {
    asm volatile(
        "mma.sync.aligned.m16n8k16.row.col.f32.f16.f16.f32 "
        "{%0,%1,%2,%3}, {%4,%5,%6,%7}, {%8,%9}, {%0,%1,%2,%3};"
        : "+f"(c.x), "+f"(c.y), "+f"(c.z), "+f"(c.w)
        : "r"(a0), "r"(a1), "r"(a2), "r"(a3), "r"(b0), "r"(b1));
}

// ---------------------------------------------------------------------------
__global__ void xform_init_kernel(const float* __restrict__ X,
                                  const float* __restrict__ W0,
                                  const float* __restrict__ W1,
                                  const float* __restrict__ W2,
                                  const int* __restrict__ eiw, int forced,
                                  const float* We0, const float* ae0,
                                  const float* We1, const float* ae1,
                                  const float* We2, const float* ae2,
                                  int M) {
    int f = blockIdx.x * blockDim.x + threadIdx.x;
    if (blockIdx.x == 0) {
        if (threadIdx.x == 0) {
            if (forced >= 0) g_is64 = forced;
            else {
                int is64 = 1;
                for (int j = 1; j < 32; j += 2)
                    if (eiw[j] != 0) is64 = 0;
                g_is64 = is64;
            }
        }
        int t = (int)threadIdx.x - 32;
        if (t >= 0 && t < 24) {
            int l = t / 8, j = t % 8;
            const float* We = (l == 0) ? We0 : (l == 1) ? We1 : We2;
            const float* ae = (l == 0) ? ae0 : (l == 1) ? ae1 : ae2;
            int C = (l == 2) ? 64 : 128;
            float s = 0.f;
            for (int c = 0; c < C; c++) s += We[j * C + c] * ae[c];
            g_v[l * 8 + j] = s;
        }
    }
    if (f < M * 32) {
        int r = f >> 5;
        int k0 = (f & 31) << 2;
        float4 v = *(const float4*)(X + (size_t)r * 128 + k0);
        int p = k0 >> 5, o = (k0 >> 4) & 1, kk = k0 & 15;
        int i = (kk >= 8) ? 1 : 0;
        int tq = (kk & 7) >> 1;
        int hb = p * 32 + tq * 8 + o * 4 + i * 2;
        __half2* hp = (__half2*)(g_xf + (size_t)r * 128);
        hp[hb >> 1]       = __floats2half2_rn(v.x, v.y);
        hp[(hb >> 1) + 4] = __floats2half2_rn(v.z, v.w);
        return;
    }
    int idx = f - M * 32;
    if (idx < 40960) {
        int l, e;
        if (idx < 16384)       { l = 0; e = idx; }
        else if (idx < 32768)  { l = 1; e = idx - 16384; }
        else                   { l = 2; e = idx - 32768; }
        int BN = (l == 2) ? 64 : 128;
        int k = e / BN, n = e % BN;
        const float* W = (l == 0) ? W0 : (l == 1) ? W1 : W2;
        __half* Wf = (l == 0) ? g_wf0 : (l == 1) ? g_wf1 : g_wf2;
        int p = k >> 5, o = (k >> 4) & 1, kk = k & 15;
        int i = (kk >= 8) ? 1 : 0;
        int tq = (kk & 7) >> 1, hs = k & 1;
        int lane = (n & 7) * 4 + tq;
        int word = ((n >> 3) * 4 + p) * 128 + lane * 4 + o * 2 + i;
        Wf[word * 2 + hs] = __float2half(W[k * BN + n]);
        return;
    }
    int i2 = idx - 40960;
    if (i2 < MAXN) g_deg[i2] = 0;
}

__global__ void count_kernel(const void* __restrict__ ei, int E, int n) {
    int e = blockIdx.x * blockDim.x + threadIdx.x;
    if (e >= E) return;
    int d = get_idx(ei, E + e);
    if ((unsigned)d < (unsigned)n) atomicAdd(&g_deg[d], 1);
}

__global__ void scan_kernel(int n) {
    __shared__ int wsum[32];
    __shared__ int carry;
    int tid = threadIdx.x, lane = tid & 31, wid = tid >> 5;
    if (tid == 0) carry = 0;
    __syncthreads();
    for (int base = 0; base < MAXN; base += 4096) {
        int i0 = base + tid * 4;
        int4 v = make_int4(0, 0, 0, 0);
        bool ok = (i0 + 3 < MAXN);
        if (ok) v = *(const int4*)&g_deg[i0];
        int s = v.x + v.y + v.z + v.w;
        int incl = s;
#pragma unroll
        for (int o = 1; o < 32; o <<= 1) {
            int t = __shfl_up_sync(0xffffffffu, incl, o);
            if (lane >= o) incl += t;
        }
        if (lane == 31) wsum[wid] = incl;
        __syncthreads();
        if (wid == 0) {
            int w = wsum[lane];
#pragma unroll
            for (int o = 1; o < 32; o <<= 1) {
                int t = __shfl_up_sync(0xffffffffu, w, o);
                if (lane >= o) w += t;
            }
            wsum[lane] = w;
        }
        __syncthreads();
        int excl = carry + incl - s + ((wid > 0) ? wsum[wid - 1] : 0);
        if (ok) {
            int4 o4;
            o4.x = excl;
            o4.y = o4.x + v.x;
            o4.z = o4.y + v.y;
            o4.w = o4.z + v.z;
            *(int4*)&g_off[i0] = o4;
            *(int4*)&g_cur[i0] = o4;
        }
        int total = wsum[31];
        __syncthreads();
        if (tid == 0) carry += total;
        __syncthreads();
    }
}

// ---------------------------------------------------------------------------
__device__ __forceinline__ void edgefill_body(const float* __restrict__ ea,
                                              const void* __restrict__ ei,
                                              int e, int E, int n) {
    if (e >= E) return;
    int s = get_idx(ei, e);
    int d = get_idx(ei, E + e);
    if ((unsigned)d >= (unsigned)n || (unsigned)s >= (unsigned)n) return;
    float a[8];
#pragma unroll
    for (int j = 0; j < 8; j++) a[j] = ea[e * 8 + j];
    float c[3];
#pragma unroll
    for (int l = 0; l < 3; l++) {
        float sv = 0.f;
#pragma unroll
        for (int j = 0; j < 8; j++) sv += a[j] * g_v[l * 8 + j];
        c[l] = sv;
    }
    int p = atomicAdd(&g_cur[d], 1);
    if (p >= MAXE) return;
    g_csr[p] = make_int4(s, __float_as_int(c[0]), __float_as_int(c[1]),
                         __float_as_int(c[2]));
}

// ---------------------------------------------------------------------------
template <int BN>
__device__ __forceinline__ void gemm_body(const __half* __restrict__ Af,
                                          const __half* __restrict__ Wf,
                                          const float* __restrict__ as_,
                                          const float* __restrict__ ad_,
                                          __half* __restrict__ H, int M,
                                          int bid) {
    const int MI = (BN == 128) ? 2 : 1;
    const int RPW = (BN == 128) ? 32 : 16;
    __shared__ float Sp[512];
    int tid = threadIdx.x;
    int lane = tid & 31, wid = tid >> 5;
    int g = lane >> 2, tq = lane & 3;
    int wr = (BN == 128) ? (wid & 3) : wid;
    int wc = (BN == 128) ? (wid >> 2) : 0;
    int row0 = bid * 128;

    float4 acc[MI][8];
#pragma unroll
    for (int mi = 0; mi < MI; mi++)
#pragma unroll
        for (int nt = 0; nt < 8; nt++) acc[mi][nt] = make_float4(0.f, 0.f, 0.f, 0.f);

    const uint4* pa[MI][2];
#pragma unroll
    for (int mi = 0; mi < MI; mi++) {
        int rb = row0 + wr * RPW + mi * 16;
        pa[mi][0] = (const uint4*)Af + (size_t)(rb + g) * 16 + tq;
        pa[mi][1] = (const uint4*)Af + (size_t)(rb + g + 8) * 16 + tq;
    }
    const uint4* pb = (const uint4*)Wf + (size_t)(wc * 8 * 4) * 32 + lane;

#pragma unroll
    for (int p = 0; p < 4; p++) {
        uint4 qa[MI], qb[MI];
#pragma unroll
        for (int mi = 0; mi < MI; mi++) {
            qa[mi] = pa[mi][0][p * 4];
            qb[mi] = pa[mi][1][p * 4];
        }
#pragma unroll
        for (int nt = 0; nt < 8; nt++) {
            uint4 w = pb[(nt * 4 + p) * 32];
#pragma unroll
            for (int mi = 0; mi < MI; mi++) {
                mma_f16(acc[mi][nt], qa[mi].x, qb[mi].x, qa[mi].y, qb[mi].y,
                        w.x, w.y);
                mma_f16(acc[mi][nt], qa[mi].z, qb[mi].z, qa[mi].w, qb[mi].w,
                        w.z, w.w);
            }
        }
    }

    float s1l[MI], s2l[MI], s1h[MI], s2h[MI];
#pragma unroll
    for (int mi = 0; mi < MI; mi++) { s1l[mi]=s2l[mi]=s1h[mi]=s2h[mi]=0.f; }
#pragma unroll
    for (int mi = 0; mi < MI; mi++) {
        int rA = row0 + wr * RPW + mi * 16 + g;
#pragma unroll
        for (int nt = 0; nt < 8; nt++) {
            int c0 = wc * 64 + nt * 8 + 2 * tq;
            float w1 = as_[c0], w1b = as_[c0 + 1];
            float w2 = ad_[c0], w2b = ad_[c0 + 1];
            float4 c = acc[mi][nt];
            s1l[mi] += c.x * w1 + c.y * w1b;
            s2l[mi] += c.x * w2 + c.y * w2b;
            s1h[mi] += c.z * w1 + c.w * w1b;
            s2h[mi] += c.z * w2 + c.w * w2b;
            if (rA < M)
                *(__half2*)&H[(size_t)rA * BN + c0] = __floats2half2_rn(c.x, c.y);
            if (rA + 8 < M)
                *(__half2*)&H[(size_t)(rA + 8) * BN + c0] = __floats2half2_rn(c.z, c.w);
        }
    }
#pragma unroll
    for (int mi = 0; mi < MI; mi++) {
#pragma unroll
        for (int o = 1; o < 4; o <<= 1) {
            s1l[mi] += __shfl_xor_sync(0xffffffffu, s1l[mi], o);
            s2l[mi] += __shfl_xor_sync(0xffffffffu, s2l[mi], o);
            s1h[mi] += __shfl_xor_sync(0xffffffffu, s1h[mi], o);
            s2h[mi] += __shfl_xor_sync(0xffffffffu, s2h[mi], o);
        }
    }
    if (BN == 64) {
        if (tq == 0) {
            int rA = row0 + wr * RPW + g;
            if (rA < M)     { g_ss[rA] = s1l[0];     g_sd[rA] = s2l[0]; }
            if (rA + 8 < M) { g_ss[rA + 8] = s1h[0]; g_sd[rA + 8] = s2h[0]; }
        }
    } else {
        if (tq == 0) {
#pragma unroll
            for (int mi = 0; mi < MI; mi++) {
                int rib = wr * RPW + mi * 16 + g;
                Sp[wc * 128 + rib]           = s1l[mi];
                Sp[wc * 128 + rib + 8]       = s1h[mi];
                Sp[256 + wc * 128 + rib]     = s2l[mi];
                Sp[256 + wc * 128 + rib + 8] = s2h[mi];
            }
        }
        __syncthreads();
        if (tid < 128) {
            int r = row0 + tid;
            if (r < M) {
                g_ss[r] = Sp[tid] + Sp[128 + tid];
                g_sd[r] = Sp[256 + tid] + Sp[384 + tid];
            }
        }
    }
}

template <int BN>
__global__ void __launch_bounds__(256, 2)
gemm_frag(const __half* __restrict__ Af, const __half* __restrict__ Wf,
          const float* __restrict__ as_, const float* __restrict__ ad_,
          __half* __restrict__ H, int M) {
    gemm_body<BN>(Af, Wf, as_, ad_, H, M, blockIdx.x);
}

__global__ void __launch_bounds__(256, 2)
gemm0_edgefill(const __half* __restrict__ Af, const __half* __restrict__ Wf,
               const float* __restrict__ as_, const float* __restrict__ ad_,
               __half* __restrict__ H, int M, int gb,
               const float* __restrict__ ea, const void* __restrict__ ei,
               int E, int n) {
    if ((int)blockIdx.x < gb) {
        gemm_body<128>(Af, Wf, as_, ad_, H, M, blockIdx.x);
    } else {
        int e = (blockIdx.x - gb) * 256 + threadIdx.x;
        edgefill_body(ea, ei, e, E, n);
    }
}

// ---------------------------------------------------------------------------
// Half-warp (16 lanes) per node; SEGMENT-MASK shuffles (divergence-safe).
__global__ void aggregate128(int layer, const float* __restrict__ bias,
                             __half* __restrict__ outf, int n) {
    int node = blockIdx.x * (blockDim.x >> 4) + (threadIdx.x >> 4);
    int lane = threadIdx.x & 31;
    int l16 = lane & 15;
    unsigned seg = 0xFFFFu << (lane & 16);   // this half-warp's lanes
    if (node >= n) return;
    int e0 = g_off[node], e1 = g_off[node + 1];
    float sdn = g_sd[node];

    float denom = 0.f, csum = 0.f;
    float acc[8];
#pragma unroll
    for (int i = 0; i < 8; i++) acc[i] = 0.f;

    for (int jb = e0; jb < e1; jb += 16) {
        int j = jb + l16;
        float ex = 0.f;
        int s = 0;
        if (j < e1) {
            int4 pe = g_csr[j];
            s = pe.x;
            float cv = __int_as_float(layer == 0 ? pe.y : (layer == 1 ? pe.z : pe.w));
            csum += cv;
            float a = g_ss[s] + sdn + cv;
            a = (a > 0.f) ? a : 0.2f * a;
            ex = __expf(a);
            denom += ex;
        }
        int kmax = min(e1 - jb, 16);
        for (int k = 0; k < kmax; k += 4) {
            float ef[4]; int sv[4];
#pragma unroll
            for (int t = 0; t < 4; t++) {
                ef[t] = __shfl_sync(seg, ex, k + t, 16);
                sv[t] = __shfl_sync(seg, s, k + t, 16);
            }
            uint4 hv[4];
#pragma unroll
            for (int t = 0; t < 4; t++)
                hv[t] = ((const uint4*)(g_h + (size_t)sv[t] * 128))[l16];
#pragma unroll
            for (int t = 0; t < 4; t++) {
                float2 f0 = __half22float2(*(const __half2*)&hv[t].x);
                float2 f1 = __half22float2(*(const __half2*)&hv[t].y);
                float2 f2 = __half22float2(*(const __half2*)&hv[t].z);
                float2 f3 = __half22float2(*(const __half2*)&hv[t].w);
                acc[0] += ef[t] * f0.x; acc[1] += ef[t] * f0.y;
                acc[2] += ef[t] * f1.x; acc[3] += ef[t] * f1.y;
                acc[4] += ef[t] * f2.x; acc[5] += ef[t] * f2.y;
                acc[6] += ef[t] * f3.x; acc[7] += ef[t] * f3.y;
            }
        }
    }
#pragma unroll
    for (int o = 8; o; o >>= 1) {
        csum  += __shfl_xor_sync(seg, csum, o);
        denom += __shfl_xor_sync(seg, denom, o);
    }
    float invd = 1.f / fmaxf((float)(e1 - e0), 1.f);
    float aself = g_ss[node] + sdn + csum * invd;
    aself = (aself > 0.f) ? aself : 0.2f * aself;
    float exs = __expf(aself);
    denom += exs;
    {
        uint4 hv = ((const uint4*)(g_h + (size_t)node * 128))[l16];
        float2 f0 = __half22float2(*(const __half2*)&hv.x);
        float2 f1 = __half22float2(*(const __half2*)&hv.y);
        float2 f2 = __half22float2(*(const __half2*)&hv.z);
        float2 f3 = __half22float2(*(const __half2*)&hv.w);
        acc[0] += exs * f0.x; acc[1] += exs * f0.y;
        acc[2] += exs * f1.x; acc[3] += exs * f1.y;
        acc[4] += exs * f2.x; acc[5] += exs * f2.y;
        acc[6] += exs * f3.x; acc[7] += exs * f3.y;
    }
    float inv = 1.f / (denom + 1e-16f);
    int c0 = l16 * 8;
    float4 b0 = *(const float4*)(bias + c0);
    float4 b1 = *(const float4*)(bias + c0 + 4);
    float r[8];
    r[0] = fmaxf(acc[0] * inv + b0.x, 0.f);
    r[1] = fmaxf(acc[1] * inv + b0.y, 0.f);
    r[2] = fmaxf(acc[2] * inv + b0.z, 0.f);
    r[3] = fmaxf(acc[3] * inv + b0.w, 0.f);
    r[4] = fmaxf(acc[4] * inv + b1.x, 0.f);
    r[5] = fmaxf(acc[5] * inv + b1.y, 0.f);
    r[6] = fmaxf(acc[6] * inv + b1.z, 0.f);
    r[7] = fmaxf(acc[7] * inv + b1.w, 0.f);
    int p = l16 >> 2, o = (l16 >> 1) & 1, i = l16 & 1;
    __half2* op = (__half2*)(outf + (size_t)node * 128);
    int base = p * 16 + o * 2 + i;
    op[base]      = __floats2half2_rn(r[0], r[1]);
    op[base + 4]  = __floats2half2_rn(r[2], r[3]);
    op[base + 8]  = __floats2half2_rn(r[4], r[5]);
    op[base + 12] = __floats2half2_rn(r[6], r[7]);
}

__global__ void aggregate64(int layer, const float* __restrict__ bias,
                            float* __restrict__ out, int n) {
    int node = blockIdx.x * (blockDim.x >> 4) + (threadIdx.x >> 4);
    int lane = threadIdx.x & 31;
    int l16 = lane & 15;
    unsigned seg = 0xFFFFu << (lane & 16);
    if (node >= n) return;
    int e0 = g_off[node], e1 = g_off[node + 1];
    float sdn = g_sd[node];

    float denom = 0.f, csum = 0.f;
    float acc[4];
#pragma unroll
    for (int i = 0; i < 4; i++) acc[i] = 0.f;

    for (int jb = e0; jb < e1; jb += 16) {
        int j = jb + l16;
        float ex = 0.f;
        int s = 0;
        if (j < e1) {
            int4 pe = g_csr[j];
            s = pe.x;
            float cv = __int_as_float(layer == 0 ? pe.y : (layer == 1 ? pe.z : pe.w));
            csum += cv;
            float a = g_ss[s] + sdn + cv;
            a = (a > 0.f) ? a : 0.2f * a;
            ex = __expf(a);
            denom += ex;
        }
        int kmax = min(e1 - jb, 16);
        for (int k = 0; k < kmax; k += 4) {
            float ef[4]; int sv[4];
#pragma unroll
            for (int t = 0; t < 4; t++) {
                ef[t] = __shfl_sync(seg, ex, k + t, 16);
                sv[t] = __shfl_sync(seg, s, k + t, 16);
            }
            uint2 hv[4];
#pragma unroll
            for (int t = 0; t < 4; t++)
                hv[t] = ((const uint2*)(g_h + (size_t)sv[t] * 64))[l16];
#pragma unroll
            for (int t = 0; t < 4; t++) {
                float2 f0 = __half22float2(*(const __half2*)&hv[t].x);
                float2 f1 = __half22float2(*(const __half2*)&hv[t].y);
                acc[0] += ef[t] * f0.x; acc[1] += ef[t] * f0.y;
                acc[2] += ef[t] * f1.x; acc[3] += ef[t] * f1.y;
            }
        }
    }
#pragma unroll
    for (int o = 8; o; o >>= 1) {
        csum  += __shfl_xor_sync(seg, csum, o);
        denom += __shfl_xor_sync(seg, denom, o);
    }
    float invd = 1.f / fmaxf((float)(e1 - e0), 1.f);
    float aself = g_ss[node] + sdn + csum * invd;
    aself = (aself > 0.f) ? aself : 0.2f * aself;
    float exs = __expf(aself);
    denom += exs;
    {
        uint2 hv = ((const uint2*)(g_h + (size_t)node * 64))[l16];
        float2 f0 = __half22float2(*(const __half2*)&hv.x);
        float2 f1 = __half22float2(*(const __half2*)&hv.y);
        acc[0] += exs * f0.x; acc[1] += exs * f0.y;
        acc[2] += exs * f1.x; acc[3] += exs * f1.y;
    }
    float inv = 1.f / (denom + 1e-16f);
    float4 b = *(const float4*)(bias + l16 * 4);
    float4 r;
    r.x = acc[0] * inv + b.x;
    r.y = acc[1] * inv + b.y;
    r.z = acc[2] * inv + b.z;
    r.w = acc[3] * inv + b.w;
    *(float4*)(out + (size_t)node * 64 + l16 * 4) = r;
}

extern "C" void kernel_launch(void* const* d_in, const int* in_sizes, int n_in,
                              void* d_out, int out_size) {
    const float* x      = (const float*)d_in[0];
    const void*  ei     = d_in[1];
    const float* ea     = (const float*)d_in[2];
    const float* W[3]  = {(const float*)d_in[3],  (const float*)d_in[9],  (const float*)d_in[15]};
    const float* As_[3]= {(const float*)d_in[4],  (const float*)d_in[10], (const float*)d_in[16]};
    const float* Ad[3] = {(const float*)d_in[5],  (const float*)d_in[11], (const float*)d_in[17]};
    const float* We[3] = {(const float*)d_in[6],  (const float*)d_in[12], (const float*)d_in[18]};
    const float* Ae[3] = {(const float*)d_in[7],  (const float*)d_in[13], (const float*)d_in[19]};
    const float* Bb[3] = {(const float*)d_in[8],  (const float*)d_in[14], (const float*)d_in[20]};

    int N = in_sizes[0] / 128;
    int E = in_sizes[2] / 8;
    int forced = (in_sizes[1] == 4 * E) ? 1 : -1;

    static __half* h = nullptr;
    static __half *xf = nullptr, *bufAf = nullptr, *bufBf = nullptr;
    static __half *wf0 = nullptr, *wf1 = nullptr, *wf2 = nullptr;
    if (!h) {
        cudaGetSymbolAddress((void**)&h,     g_h);
        cudaGetSymbolAddress((void**)&xf,    g_xf);
        cudaGetSymbolAddress((void**)&bufAf, g_bufAf);
        cudaGetSymbolAddress((void**)&bufBf, g_bufBf);
        cudaGetSymbolAddress((void**)&wf0,   g_wf0);
        cudaGetSymbolAddress((void**)&wf1,   g_wf1);
        cudaGetSymbolAddress((void**)&wf2,   g_wf2);
    }

    int gb = (N + 127) / 128;
    int nb = (N + 15) / 16;
    int eb = (E + 255) / 256;

    xform_init_kernel<<<(N * 32 + 40960 + MAXN + 255) / 256, 256>>>(
        x, W[0], W[1], W[2], (const int*)ei, forced,
        We[0], Ae[0], We[1], Ae[1], We[2], Ae[2], N);
    count_kernel<<<eb, 256>>>(ei, E, N);
    scan_kernel<<<1, 1024>>>(N);
    gemm0_edgefill<<<gb + eb, 256>>>(xf, wf0, As_[0], Ad[0], h, N, gb,
                                     ea, ei, E, N);
    aggregate128<<<nb, 256>>>(0, Bb[0], bufAf, N);
    gemm_frag<128><<<gb, 256>>>(bufAf, wf1, As_[1], Ad[1], h, N);
    aggregate128<<<nb, 256>>>(1, Bb[1], bufBf, N);
    gemm_frag<64><<<gb, 256>>>(bufBf, wf2, As_[2], Ad[2], h, N);
    aggregate64<<<nb, 256>>>(2, Bb[2], (float*)d_out, N);
}